// round 6
// baseline (speedup 1.0000x reference)
#include <cuda_runtime.h>
#include <cstdint>

// ---------------------------------------------------------------------------
// Problem constants
// ---------------------------------------------------------------------------
#define BB    2
#define CIN   256
#define HH    56
#define WW    56
#define OUTC  256
#define KK    7
#define PADV  3
#define GRP   8
#define CG    32
#define HP    62
#define WP    62
#define NQ    (HH*WW)     // 3136
#define NP    (HP*WP)     // 3844

#define KT    32          // k-tile
#define STR   36          // SMEM float stride (conflict-free frag reads)
#define CSTR  132         // epilogue transpose stride

// Q tiles: 49 n * 2 o * 2 b = 196 ; K/V tiles: 61 n * 2 o * 2 b = 244 each
#define QT    196
#define KTLS  244
#define TOT_TILES (QT + 2*KTLS)   // 684

// ---------------------------------------------------------------------------
// MMA helpers (portable sm_80+ PTX — compiles for compute_103)
// ---------------------------------------------------------------------------
__device__ __forceinline__ void mma8(float* c, const uint32_t* a, const uint32_t* b) {
    asm volatile("mma.sync.aligned.m16n8k8.row.col.f32.tf32.tf32.f32 "
        "{%0,%1,%2,%3}, {%4,%5,%6,%7}, {%8,%9}, {%0,%1,%2,%3};"
        : "+f"(c[0]), "+f"(c[1]), "+f"(c[2]), "+f"(c[3])
        : "r"(a[0]), "r"(a[1]), "r"(a[2]), "r"(a[3]), "r"(b[0]), "r"(b[1]));
}
__device__ __forceinline__ uint32_t hi_bits(float x) {
    return __float_as_uint(x) & 0xFFFFE000u;    // top-10 mantissa bits: exact tf32
}
__device__ __forceinline__ uint32_t lo_tf32(float x, uint32_t h) {
    float lo = x - __uint_as_float(h);
    uint32_t r;
    asm("cvt.rna.tf32.f32 %0, %1;" : "=r"(r) : "f"(lo));
    return r;
}
__device__ __forceinline__ void split4(float4 v, uint4& h, uint4& l) {
    h.x = hi_bits(v.x); h.y = hi_bits(v.y); h.z = hi_bits(v.z); h.w = hi_bits(v.w);
    l.x = lo_tf32(v.x, h.x); l.y = lo_tf32(v.y, h.y);
    l.z = lo_tf32(v.z, h.z); l.w = lo_tf32(v.w, h.w);
}
__device__ __forceinline__ void lda(uint32_t* f, const uint32_t* S, int mb, int k0, int r, int q) {
    f[0] = S[(mb + r)     * STR + k0 + q];
    f[1] = S[(mb + r + 8) * STR + k0 + q];
    f[2] = S[(mb + r)     * STR + k0 + q + 4];
    f[3] = S[(mb + r + 8) * STR + k0 + q + 4];
}
__device__ __forceinline__ void ldb(uint32_t* f, const uint32_t* S, int nb, int k0, int r, int q) {
    f[0] = S[(nb + r) * STR + k0 + q];
    f[1] = S[(nb + r) * STR + k0 + q + 4];
}

// ---------------------------------------------------------------------------
// Scratch (device globals)
// ---------------------------------------------------------------------------
__device__ float g_q[BB * NQ * OUTC];
__device__ float g_k[BB * NP * OUTC];
__device__ float g_v[BB * NP * OUTC];

// ---------------------------------------------------------------------------
// Fused GEMM (Q / K / V block types) via 3xTF32 mma.sync.
// Padding is folded into the K/V B-tile load (predicated scalar gathers
// from fm_t0) — no pad kernel, no g_pad buffer.
// Tile: 128(o) x 64(n); 8 warps 4(m)x2(n); warp 32x32.
// ---------------------------------------------------------------------------
#define G_SMEMB ((2*128 + 2*64) * STR * 4)     // 55296

__global__ __launch_bounds__(256, 2) void gemm_all(const float* __restrict__ fm,
                                                   const float* __restrict__ wq,
                                                   const float* __restrict__ wk,
                                                   const float* __restrict__ wv) {
    extern __shared__ uint32_t smu[];
    uint32_t* AH = smu;
    uint32_t* AL = smu + 128 * STR;
    uint32_t* BH = smu + 2 * 128 * STR;
    uint32_t* BL = smu + 2 * 128 * STR + 64 * STR;

    const int t = threadIdx.x;
    const int id = blockIdx.x;

    // decode block type + tile coords
    int local, nt;
    const float* W;
    if (id < QT)             { local = id;             nt = 49; W = wq; }
    else if (id < QT + KTLS) { local = id - QT;        nt = 61; W = wk; }
    else                     { local = id - QT - KTLS; nt = 61; W = wv; }
    const int ni_t = local % nt;
    const int rest = local / nt;          // b*2 + oi
    const int o0 = (rest & 1) * 128;
    const int b  = rest >> 1;
    const int n0 = ni_t * 64;
    const bool isQ = (id < QT);

    float* D;
    int NN;
    const float* Xq = fm + (size_t)b * (2 * CIN) * NQ + (size_t)CIN * NQ;  // fm_t1
    const float* X0 = fm + (size_t)b * (2 * CIN) * NQ;                     // fm_t0
    if (isQ) { D = g_q + (size_t)b * NQ * OUTC; NN = NQ; }
    else     { D = ((id < QT + KTLS) ? g_k : g_v) + (size_t)b * NP * OUTC; NN = NP; }

    const int wid = t >> 5, l = t & 31;
    const int m0w = (wid & 3) * 32;
    const int n0w = (wid >> 2) * 32;
    const int r = l >> 2, q = l & 3;
    const int cc = t & 31, grp = t >> 5;   // B-load role: channel cc, pixels grp*8..grp*8+7

    // Precompute padded-domain pixel gather offsets (K/V path)
    int pixoff[8];
    unsigned pmask = 0;
    if (!isQ) {
#pragma unroll
        for (int j = 0; j < 8; j++) {
            int nb = n0 + grp * 8 + j;
            int py = nb / WP - PADV;
            int px = nb % WP - PADV;
            bool v = (nb < NP) && (py >= 0) && (py < HH) && (px >= 0) && (px < WW);
            if (v) pmask |= (1u << j);
            pixoff[j] = py * WW + px;
        }
    }

    float c[2][4][4];
#pragma unroll
    for (int mi = 0; mi < 2; mi++)
#pragma unroll
        for (int ni = 0; ni < 4; ni++)
#pragma unroll
            for (int e = 0; e < 4; e++) c[mi][ni][e] = 0.f;

    for (int kt = 0; kt < CIN / KT; kt++) {
        const int c0 = kt * KT;
        // stage gmem loads in regs
        float4 av[4];
#pragma unroll
        for (int i = 0; i < 4; i++) {
            int id2 = t + i * 256;
            int m = id2 >> 3, f = id2 & 7;
            av[i] = *(const float4*)&W[(size_t)(o0 + m) * CIN + c0 + f * 4];
        }
        float bvals[8];
        if (isQ) {
            int nb = n0 + grp * 8;
            float4 b0 = *(const float4*)&Xq[(size_t)(c0 + cc) * NQ + nb];
            float4 b1 = *(const float4*)&Xq[(size_t)(c0 + cc) * NQ + nb + 4];
            bvals[0] = b0.x; bvals[1] = b0.y; bvals[2] = b0.z; bvals[3] = b0.w;
            bvals[4] = b1.x; bvals[5] = b1.y; bvals[6] = b1.z; bvals[7] = b1.w;
        } else {
            const float* row = X0 + (size_t)(c0 + cc) * NQ;
#pragma unroll
            for (int j = 0; j < 8; j++)
                bvals[j] = (pmask & (1u << j)) ? row[pixoff[j]] : 0.f;
        }
        __syncthreads();
#pragma unroll
        for (int i = 0; i < 4; i++) {
            int id2 = t + i * 256;
            int m = id2 >> 3, f = id2 & 7;
            uint4 h, lo;
            split4(av[i], h, lo);
            *(uint4*)&AH[m * STR + f * 4] = h;
            *(uint4*)&AL[m * STR + f * 4] = lo;
        }
#pragma unroll
        for (int j = 0; j < 8; j++) {
            uint32_t h = hi_bits(bvals[j]);
            BH[(grp * 8 + j) * STR + cc] = h;
            BL[(grp * 8 + j) * STR + cc] = lo_tf32(bvals[j], h);
        }
        __syncthreads();

#pragma unroll
        for (int ks = 0; ks < 4; ks++) {
            const int k0 = ks * 8;
            uint32_t ah[2][4], al[2][4];
            lda(ah[0], AH, m0w,      k0, r, q);
            lda(ah[1], AH, m0w + 16, k0, r, q);
            lda(al[0], AL, m0w,      k0, r, q);
            lda(al[1], AL, m0w + 16, k0, r, q);
#pragma unroll
            for (int ni = 0; ni < 4; ni++) {
                uint32_t bh[2], bl[2];
                ldb(bh, BH, n0w + ni * 8, k0, r, q);
                ldb(bl, BL, n0w + ni * 8, k0, r, q);
#pragma unroll
                for (int mi = 0; mi < 2; mi++) {
                    mma8(c[mi][ni], ah[mi], bh);
                    mma8(c[mi][ni], ah[mi], bl);
                    mma8(c[mi][ni], al[mi], bh);
                }
            }
        }
    }

    // Epilogue: transpose through SMEM -> coalesced channel-last stores
    __syncthreads();
    float* Ct = (float*)smu;                 // [64 n][CSTR]
#pragma unroll
    for (int mi = 0; mi < 2; mi++)
#pragma unroll
        for (int ni = 0; ni < 4; ni++) {
            int m = m0w + mi * 16 + r;
            int n = n0w + ni * 8 + q * 2;
            Ct[(n)     * CSTR + m]     = c[mi][ni][0];
            Ct[(n + 1) * CSTR + m]     = c[mi][ni][1];
            Ct[(n)     * CSTR + m + 8] = c[mi][ni][2];
            Ct[(n + 1) * CSTR + m + 8] = c[mi][ni][3];
        }
    __syncthreads();
#pragma unroll
    for (int i = 0; i < 8; i++) {
        int id2 = t + i * 256;
        int n = id2 >> 5, f = id2 & 31;
        if (n0 + n < NN) {
            float4 v = *(float4*)&Ct[n * CSTR + f * 4];
            *(float4*)&D[(size_t)(n0 + n) * OUTC + o0 + f * 4] = v;
        }
    }
}

// ---------------------------------------------------------------------------
// Attention: 256 threads/block, 4 threads per pixel (8 channels each).
// Partial logits combined with shfl.xor(1) + shfl.xor(2); softmax redundant;
// pass-2 channel-split.  SSTR=197 keeps all LDS.128 phases conflict-free.
// ---------------------------------------------------------------------------
#define TPIX   14
#define NPIX   (TPIX*TPIX)
#define SSTR   197
#define ATTN_SMEM (2 * 8 * SSTR * 16 + CG * KK * 4)   // 51328 B

__global__ __launch_bounds__(256) void attn_kernel(const float* __restrict__ relh,
                                                   const float* __restrict__ relw,
                                                   float* __restrict__ out) {
    extern __shared__ float4 smbuf[];
    float4* ks   = smbuf;
    float4* vs   = smbuf + 8 * SSTR;
    float*  bias = (float*)(smbuf + 16 * SSTR);

    const int b    = blockIdx.z;
    const int g    = blockIdx.y;
    const int tile = blockIdx.x;
    const int ty0  = (tile / 7) * 8;
    const int tx0  = (tile % 7) * 8;
    const int t    = threadIdx.x;
    const int p    = t >> 2;                    // pixel 0..63
    const int qt   = t & 3;                     // channel quarter

    const float* rel = (g < 4) ? (relh + (size_t)g * CG * KK)
                               : (relw + (size_t)(g - 4) * CG * KK);
    for (int i = t; i < CG * KK; i += 256) bias[i] = rel[i];

    for (int idx = t; idx < NPIX * 8; idx += 256) {
        int c4 = idx & 7;
        int pp = idx >> 3;
        int py = pp / TPIX, px = pp - py * TPIX;
        size_t gbase = (((size_t)b * HP + (ty0 + py)) * WP + (tx0 + px)) * OUTC + g * CG;
        ks[c4 * SSTR + pp] = *((const float4*)&g_k[gbase] + c4);
        vs[c4 * SSTR + pp] = *((const float4*)&g_v[gbase] + c4);
    }
    __syncthreads();

    const int lty = p >> 3, ltx = p & 7;
    const int h = ty0 + lty, w = tx0 + ltx;
    const int pbase = lty * TPIX + ltx;
    const int c4b = qt * 2;                     // this lane's c4 range [c4b, c4b+2)

    // own 8 q channels
    float qf[8];
    {
        const float4* qp = (const float4*)&g_q[((size_t)b * NQ + h * WW + w) * OUTC + g * CG];
#pragma unroll
        for (int c4 = 0; c4 < 2; c4++) {
            float4 v = qp[c4b + c4];
            qf[c4 * 4 + 0] = v.x; qf[c4 * 4 + 1] = v.y;
            qf[c4 * 4 + 2] = v.z; qf[c4 * 4 + 3] = v.w;
        }
    }

    // partial bias dots over own channels
    float db[KK];
#pragma unroll
    for (int i = 0; i < KK; i++) {
        float s = 0.f;
#pragma unroll
        for (int c = 0; c < 8; c++) s += qf[c] * bias[(qt * 8 + c) * KK + i];
        db[i] = s;
    }
#pragma unroll
    for (int i = 0; i < KK; i++) {
        db[i] += __shfl_xor_sync(0xffffffffu, db[i], 1);
        db[i] += __shfl_xor_sync(0xffffffffu, db[i], 2);
    }

    // pass 1: partial logits over own channels, combine across quartet
    float lg[KK * KK];
#pragma unroll
    for (int n = 0; n < KK * KK; n++) {
        const int i = n / KK, j = n % KK;
        const int pp = pbase + i * TPIX + j;
        float4 k0 = ks[(c4b)     * SSTR + pp];
        float4 k1 = ks[(c4b + 1) * SSTR + pp];
        lg[n] = qf[0] * k0.x + qf[1] * k0.y + qf[2] * k0.z + qf[3] * k0.w
              + qf[4] * k1.x + qf[5] * k1.y + qf[6] * k1.z + qf[7] * k1.w;
    }
#pragma unroll
    for (int n = 0; n < KK * KK; n++)
        lg[n] += __shfl_xor_sync(0xffffffffu, lg[n], 1);
#pragma unroll
    for (int n = 0; n < KK * KK; n++)
        lg[n] += __shfl_xor_sync(0xffffffffu, lg[n], 2);
#pragma unroll
    for (int n = 0; n < KK * KK; n++)
        lg[n] += (g < 4) ? db[n / KK] : db[n % KK];

    // softmax (redundant on the 4 lanes of the quartet)
    float mx = lg[0];
#pragma unroll
    for (int n = 1; n < KK * KK; n++) mx = fmaxf(mx, lg[n]);
    float sum = 0.f;
#pragma unroll
    for (int n = 0; n < KK * KK; n++) { lg[n] = __expf(lg[n] - mx); sum += lg[n]; }
    float inv = 1.f / sum;
#pragma unroll
    for (int n = 0; n < KK * KK; n++) lg[n] *= inv;

    // pass 2: own channel pair only
#pragma unroll
    for (int c4 = 0; c4 < 2; c4++) {
        float4 acc = make_float4(0.f, 0.f, 0.f, 0.f);
#pragma unroll
        for (int n = 0; n < KK * KK; n++) {
            const int pp = pbase + (n / KK) * TPIX + (n % KK);
            float4 vv = vs[(c4b + c4) * SSTR + pp];
            acc.x += lg[n] * vv.x;
            acc.y += lg[n] * vv.y;
            acc.z += lg[n] * vv.z;
            acc.w += lg[n] * vv.w;
        }
        size_t base = ((size_t)(b * OUTC + g * CG + (c4b + c4) * 4)) * NQ + h * WW + w;
        out[base]          = acc.x;
        out[base + NQ]     = acc.y;
        out[base + 2 * NQ] = acc.z;
        out[base + 3 * NQ] = acc.w;
    }
}

// ---------------------------------------------------------------------------
// Launch
// ---------------------------------------------------------------------------
extern "C" void kernel_launch(void* const* d_in, const int* in_sizes, int n_in,
                              void* d_out, int out_size) {
    const float* fm = (const float*)d_in[0];
    const float* wq = (const float*)d_in[1];
    const float* wk = (const float*)d_in[2];
    const float* wv = (const float*)d_in[3];
    const float* rh = (const float*)d_in[4];
    const float* rw = (const float*)d_in[5];
    float* out = (float*)d_out;

    cudaFuncSetAttribute(attn_kernel, cudaFuncAttributeMaxDynamicSharedMemorySize, ATTN_SMEM);
    cudaFuncSetAttribute(gemm_all,    cudaFuncAttributeMaxDynamicSharedMemorySize, G_SMEMB);

    gemm_all<<<TOT_TILES, 256, G_SMEMB>>>(fm, wq, wk, wv);
    attn_kernel<<<dim3(49, GRP, BB), 256, ATTN_SMEM>>>(rh, rw, out);
}

// round 7
// speedup vs baseline: 1.2948x; 1.2948x over previous
#include <cuda_runtime.h>
#include <cstdint>

// ---------------------------------------------------------------------------
// Problem constants
// ---------------------------------------------------------------------------
#define BB    2
#define CIN   256
#define HH    56
#define WW    56
#define OUTC  256
#define KK    7
#define PADV  3
#define GRP   8
#define CG    32
#define NQ    (HH*WW)     // 3136 = 49*64

#define KT    32          // k-tile
#define STR   36          // SMEM float stride (conflict-free frag reads)
#define CSTR  132         // epilogue transpose stride

// All GEMMs now over NQ: 49 n-tiles * 2 o * 2 b = 196 per type, 3 types
#define TPB   196
#define TOT_TILES (3*TPB) // 588

// ---------------------------------------------------------------------------
// MMA helpers (portable sm_80+ PTX — compiles for compute_103)
// ---------------------------------------------------------------------------
__device__ __forceinline__ void mma8(float* c, const uint32_t* a, const uint32_t* b) {
    asm volatile("mma.sync.aligned.m16n8k8.row.col.f32.tf32.tf32.f32 "
        "{%0,%1,%2,%3}, {%4,%5,%6,%7}, {%8,%9}, {%0,%1,%2,%3};"
        : "+f"(c[0]), "+f"(c[1]), "+f"(c[2]), "+f"(c[3])
        : "r"(a[0]), "r"(a[1]), "r"(a[2]), "r"(a[3]), "r"(b[0]), "r"(b[1]));
}
__device__ __forceinline__ uint32_t hi_bits(float x) {
    return __float_as_uint(x) & 0xFFFFE000u;    // top-10 mantissa bits: exact tf32
}
__device__ __forceinline__ uint32_t lo_tf32(float x, uint32_t h) {
    float lo = x - __uint_as_float(h);
    uint32_t r;
    asm("cvt.rna.tf32.f32 %0, %1;" : "=r"(r) : "f"(lo));
    return r;
}
__device__ __forceinline__ void split4(float4 v, uint4& h, uint4& l) {
    h.x = hi_bits(v.x); h.y = hi_bits(v.y); h.z = hi_bits(v.z); h.w = hi_bits(v.w);
    l.x = lo_tf32(v.x, h.x); l.y = lo_tf32(v.y, h.y);
    l.z = lo_tf32(v.z, h.z); l.w = lo_tf32(v.w, h.w);
}
__device__ __forceinline__ void lda(uint32_t* f, const uint32_t* S, int mb, int k0, int r, int q) {
    f[0] = S[(mb + r)     * STR + k0 + q];
    f[1] = S[(mb + r + 8) * STR + k0 + q];
    f[2] = S[(mb + r)     * STR + k0 + q + 4];
    f[3] = S[(mb + r + 8) * STR + k0 + q + 4];
}
__device__ __forceinline__ void ldb(uint32_t* f, const uint32_t* S, int nb, int k0, int r, int q) {
    f[0] = S[(nb + r) * STR + k0 + q];
    f[1] = S[(nb + r) * STR + k0 + q + 4];
}

// ---------------------------------------------------------------------------
// Scratch (device globals) — all channel-last over the 56x56 domain
// ---------------------------------------------------------------------------
__device__ float g_q[BB * NQ * OUTC];
__device__ float g_k[BB * NQ * OUTC];
__device__ float g_v[BB * NQ * OUTC];

// ---------------------------------------------------------------------------
// Fused GEMM (Q / K / V block types) via 3xTF32 mma.sync — uniform tiles,
// no padded domain, no bounds checks (NQ = 49*64 exactly).
// Tile: 128(o) x 64(n); 8 warps 4(m)x2(n); warp 32x32.
// ---------------------------------------------------------------------------
#define G_SMEMB ((2*128 + 2*64) * STR * 4)     // 55296

__global__ __launch_bounds__(256, 2) void gemm_all(const float* __restrict__ fm,
                                                   const float* __restrict__ wq,
                                                   const float* __restrict__ wk,
                                                   const float* __restrict__ wv) {
    extern __shared__ uint32_t smu[];
    uint32_t* AH = smu;
    uint32_t* AL = smu + 128 * STR;
    uint32_t* BH = smu + 2 * 128 * STR;
    uint32_t* BL = smu + 2 * 128 * STR + 64 * STR;

    const int t  = threadIdx.x;
    const int id = blockIdx.x;

    const int type  = id / TPB;           // 0=Q, 1=K, 2=V
    const int local = id % TPB;
    const int ni_t = local % 49;
    const int rest = local / 49;          // b*2 + oi
    const int o0 = (rest & 1) * 128;
    const int b  = rest >> 1;
    const int n0 = ni_t * 64;

    const float* W = (type == 0) ? wq : (type == 1) ? wk : wv;
    // Q reads fm_t1 (channels [256,512)); K/V read fm_t0 (channels [0,256))
    const float* X = fm + (size_t)b * (2 * CIN) * NQ + (type == 0 ? (size_t)CIN * NQ : 0);
    float* D = ((type == 0) ? g_q : (type == 1) ? g_k : g_v) + (size_t)b * NQ * OUTC;

    const int wid = t >> 5, l = t & 31;
    const int m0w = (wid & 3) * 32;
    const int n0w = (wid >> 2) * 32;
    const int r = l >> 2, q = l & 3;
    const int cc = t & 31, grp = t >> 5;   // B-load: channel cc, pixels grp*8..grp*8+7

    float c[2][4][4];
#pragma unroll
    for (int mi = 0; mi < 2; mi++)
#pragma unroll
        for (int ni = 0; ni < 4; ni++)
#pragma unroll
            for (int e = 0; e < 4; e++) c[mi][ni][e] = 0.f;

    for (int kt = 0; kt < CIN / KT; kt++) {
        const int c0 = kt * KT;
        // stage gmem loads in regs (overlap previous iteration's MMA tail)
        float4 av[4];
#pragma unroll
        for (int i = 0; i < 4; i++) {
            int id2 = t + i * 256;
            int m = id2 >> 3, f = id2 & 7;
            av[i] = *(const float4*)&W[(size_t)(o0 + m) * CIN + c0 + f * 4];
        }
        float4 bv0, bv1;
        {
            int nb = n0 + grp * 8;
            bv0 = *(const float4*)&X[(size_t)(c0 + cc) * NQ + nb];
            bv1 = *(const float4*)&X[(size_t)(c0 + cc) * NQ + nb + 4];
        }
        __syncthreads();
#pragma unroll
        for (int i = 0; i < 4; i++) {
            int id2 = t + i * 256;
            int m = id2 >> 3, f = id2 & 7;
            uint4 h, lo;
            split4(av[i], h, lo);
            *(uint4*)&AH[m * STR + f * 4] = h;
            *(uint4*)&AL[m * STR + f * 4] = lo;
        }
        {
            uint4 h, lo;
            int nb = grp * 8;
            split4(bv0, h, lo);
            BH[(nb + 0) * STR + cc] = h.x;  BL[(nb + 0) * STR + cc] = lo.x;
            BH[(nb + 1) * STR + cc] = h.y;  BL[(nb + 1) * STR + cc] = lo.y;
            BH[(nb + 2) * STR + cc] = h.z;  BL[(nb + 2) * STR + cc] = lo.z;
            BH[(nb + 3) * STR + cc] = h.w;  BL[(nb + 3) * STR + cc] = lo.w;
            split4(bv1, h, lo);
            BH[(nb + 4) * STR + cc] = h.x;  BL[(nb + 4) * STR + cc] = lo.x;
            BH[(nb + 5) * STR + cc] = h.y;  BL[(nb + 5) * STR + cc] = lo.y;
            BH[(nb + 6) * STR + cc] = h.z;  BL[(nb + 6) * STR + cc] = lo.z;
            BH[(nb + 7) * STR + cc] = h.w;  BL[(nb + 7) * STR + cc] = lo.w;
        }
        __syncthreads();

#pragma unroll
        for (int ks = 0; ks < 4; ks++) {
            const int k0 = ks * 8;
            uint32_t ah[2][4], al[2][4];
            lda(ah[0], AH, m0w,      k0, r, q);
            lda(ah[1], AH, m0w + 16, k0, r, q);
            lda(al[0], AL, m0w,      k0, r, q);
            lda(al[1], AL, m0w + 16, k0, r, q);
#pragma unroll
            for (int ni = 0; ni < 4; ni++) {
                uint32_t bh[2], bl[2];
                ldb(bh, BH, n0w + ni * 8, k0, r, q);
                ldb(bl, BL, n0w + ni * 8, k0, r, q);
#pragma unroll
                for (int mi = 0; mi < 2; mi++) {
                    mma8(c[mi][ni], ah[mi], bh);
                    mma8(c[mi][ni], ah[mi], bl);
                    mma8(c[mi][ni], al[mi], bh);
                }
            }
        }
    }

    // Epilogue: transpose through SMEM -> coalesced channel-last stores
    __syncthreads();
    float* Ct = (float*)smu;                 // [64 n][CSTR]
#pragma unroll
    for (int mi = 0; mi < 2; mi++)
#pragma unroll
        for (int ni = 0; ni < 4; ni++) {
            int m = m0w + mi * 16 + r;
            int n = n0w + ni * 8 + q * 2;
            Ct[(n)     * CSTR + m]     = c[mi][ni][0];
            Ct[(n + 1) * CSTR + m]     = c[mi][ni][1];
            Ct[(n)     * CSTR + m + 8] = c[mi][ni][2];
            Ct[(n + 1) * CSTR + m + 8] = c[mi][ni][3];
        }
    __syncthreads();
#pragma unroll
    for (int i = 0; i < 8; i++) {
        int id2 = t + i * 256;
        int n = id2 >> 5, f = id2 & 31;
        float4 v = *(float4*)&Ct[n * CSTR + f * 4];
        *(float4*)&D[(size_t)(n0 + n) * OUTC + o0 + f * 4] = v;
    }
}

// ---------------------------------------------------------------------------
// Attention: 128 threads, 2 threads/pixel (channel halves), single SMEM
// buffer reused K -> V (halves SMEM to 26.1 KB -> higher occupancy).
// Halo pixels outside the 56x56 domain are zero-filled at load time
// (exactly matches reference: conv of zero padding is zero).
// ---------------------------------------------------------------------------
#define TPIX   14
#define NPIX   (TPIX*TPIX)
#define SSTR   197
#define ATTN_SMEM (8 * SSTR * 16 + CG * KK * 4)   // 25216 + 896 = 26112 B

__global__ __launch_bounds__(128, 4) void attn_kernel(const float* __restrict__ relh,
                                                      const float* __restrict__ relw,
                                                      float* __restrict__ out) {
    extern __shared__ float4 smbuf[];
    float4* buf  = smbuf;                        // [8][SSTR], K then V
    float*  bias = (float*)(smbuf + 8 * SSTR);   // [32][7]

    const int b    = blockIdx.z;
    const int g    = blockIdx.y;
    const int tile = blockIdx.x;
    const int ty0  = (tile / 7) * 8;             // padded-domain tile origin
    const int tx0  = (tile % 7) * 8;
    const int t    = threadIdx.x;
    const int p    = t >> 1;                     // pixel 0..63
    const int half = t & 1;                      // channel half

    const float* rel = (g < 4) ? (relh + (size_t)g * CG * KK)
                               : (relw + (size_t)(g - 4) * CG * KK);
    for (int i = t; i < CG * KK; i += 128) bias[i] = rel[i];

    // ---- load K tile (zero-filled halo) ----
    for (int idx = t; idx < NPIX * 8; idx += 128) {
        int c4 = idx & 7;
        int pp = idx >> 3;
        int py = pp / TPIX, px = pp - py * TPIX;
        int yy = ty0 + py - PADV, xx = tx0 + px - PADV;
        float4 v = make_float4(0.f, 0.f, 0.f, 0.f);
        if (yy >= 0 && yy < HH && xx >= 0 && xx < WW)
            v = *((const float4*)&g_k[((size_t)b * NQ + yy * WW + xx) * OUTC + g * CG] + c4);
        buf[c4 * SSTR + pp] = v;
    }
    __syncthreads();

    const int lty = p >> 3, ltx = p & 7;
    const int h = ty0 + lty, w = tx0 + ltx;      // output pixel (0..55)
    const int pbase = lty * TPIX + ltx;
    const int c4b = half * 4;

    // own 16 q channels
    float qf[16];
    {
        const float4* qp = (const float4*)&g_q[((size_t)b * NQ + h * WW + w) * OUTC + g * CG];
#pragma unroll
        for (int c4 = 0; c4 < 4; c4++) {
            float4 v = qp[c4b + c4];
            qf[c4 * 4 + 0] = v.x; qf[c4 * 4 + 1] = v.y;
            qf[c4 * 4 + 2] = v.z; qf[c4 * 4 + 3] = v.w;
        }
    }

    // partial bias dots over own channels
    float db[KK];
#pragma unroll
    for (int i = 0; i < KK; i++) {
        float s = 0.f;
#pragma unroll
        for (int c = 0; c < 16; c++) s += qf[c] * bias[(half * 16 + c) * KK + i];
        db[i] = s;
    }
#pragma unroll
    for (int i = 0; i < KK; i++) db[i] += __shfl_xor_sync(0xffffffffu, db[i], 1);

    // pass 1: partial logits, combine across the lane pair
    float lg[KK * KK];
#pragma unroll
    for (int n = 0; n < KK * KK; n++) {
        const int i = n / KK, j = n % KK;
        const int pp = pbase + i * TPIX + j;
        float s = 0.f;
#pragma unroll
        for (int c4 = 0; c4 < 4; c4++) {
            float4 kv = buf[(c4b + c4) * SSTR + pp];
            s += qf[c4 * 4 + 0] * kv.x + qf[c4 * 4 + 1] * kv.y
               + qf[c4 * 4 + 2] * kv.z + qf[c4 * 4 + 3] * kv.w;
        }
        lg[n] = s;
    }
#pragma unroll
    for (int n = 0; n < KK * KK; n++)
        lg[n] += __shfl_xor_sync(0xffffffffu, lg[n], 1);
#pragma unroll
    for (int n = 0; n < KK * KK; n++)
        lg[n] += (g < 4) ? db[n / KK] : db[n % KK];

    // ---- buf free: load V tile ----
    __syncthreads();
    for (int idx = t; idx < NPIX * 8; idx += 128) {
        int c4 = idx & 7;
        int pp = idx >> 3;
        int py = pp / TPIX, px = pp - py * TPIX;
        int yy = ty0 + py - PADV, xx = tx0 + px - PADV;
        float4 v = make_float4(0.f, 0.f, 0.f, 0.f);
        if (yy >= 0 && yy < HH && xx >= 0 && xx < WW)
            v = *((const float4*)&g_v[((size_t)b * NQ + yy * WW + xx) * OUTC + g * CG] + c4);
        buf[c4 * SSTR + pp] = v;
    }

    // softmax (independent of buf; overlaps the V loads)
    float mx = lg[0];
#pragma unroll
    for (int n = 1; n < KK * KK; n++) mx = fmaxf(mx, lg[n]);
    float sum = 0.f;
#pragma unroll
    for (int n = 0; n < KK * KK; n++) { lg[n] = __expf(lg[n] - mx); sum += lg[n]; }
    float inv = 1.f / sum;
#pragma unroll
    for (int n = 0; n < KK * KK; n++) lg[n] *= inv;

    __syncthreads();

    // pass 2: own channel half only
#pragma unroll
    for (int c4 = 0; c4 < 4; c4++) {
        float4 acc = make_float4(0.f, 0.f, 0.f, 0.f);
#pragma unroll
        for (int n = 0; n < KK * KK; n++) {
            const int pp = pbase + (n / KK) * TPIX + (n % KK);
            float4 vv = buf[(c4b + c4) * SSTR + pp];
            acc.x += lg[n] * vv.x;
            acc.y += lg[n] * vv.y;
            acc.z += lg[n] * vv.z;
            acc.w += lg[n] * vv.w;
        }
        size_t base = ((size_t)(b * OUTC + g * CG + (c4b + c4) * 4)) * NQ + h * WW + w;
        out[base]          = acc.x;
        out[base + NQ]     = acc.y;
        out[base + 2 * NQ] = acc.z;
        out[base + 3 * NQ] = acc.w;
    }
}

// ---------------------------------------------------------------------------
// Launch
// ---------------------------------------------------------------------------
extern "C" void kernel_launch(void* const* d_in, const int* in_sizes, int n_in,
                              void* d_out, int out_size) {
    const float* fm = (const float*)d_in[0];
    const float* wq = (const float*)d_in[1];
    const float* wk = (const float*)d_in[2];
    const float* wv = (const float*)d_in[3];
    const float* rh = (const float*)d_in[4];
    const float* rw = (const float*)d_in[5];
    float* out = (float*)d_out;

    cudaFuncSetAttribute(attn_kernel, cudaFuncAttributeMaxDynamicSharedMemorySize, ATTN_SMEM);
    cudaFuncSetAttribute(gemm_all,    cudaFuncAttributeMaxDynamicSharedMemorySize, G_SMEMB);

    gemm_all<<<TOT_TILES, 256, G_SMEMB>>>(fm, wq, wk, wv);
    attn_kernel<<<dim3(49, GRP, BB), 128, ATTN_SMEM>>>(rh, rw, out);
}

// round 8
// speedup vs baseline: 1.3913x; 1.0745x over previous
#include <cuda_runtime.h>
#include <cstdint>

// ---------------------------------------------------------------------------
// Problem constants
// ---------------------------------------------------------------------------
#define BB    2
#define CIN   256
#define HH    56
#define WW    56
#define OUTC  256
#define KK    7
#define PADV  3
#define GRP   8
#define CG    32
#define NQ    (HH*WW)     // 3136 = 49*64

#define KT    32          // k-tile
#define STR   36          // SMEM float stride (conflict-free frag reads)
#define CSTR  132         // epilogue transpose stride

#define TPB   196
#define TOT_TILES (3*TPB) // 588

// ---------------------------------------------------------------------------
// MMA helpers (portable sm_80+ PTX — compiles for compute_103)
// ---------------------------------------------------------------------------
__device__ __forceinline__ void mma8(float* c, const uint32_t* a, const uint32_t* b) {
    asm volatile("mma.sync.aligned.m16n8k8.row.col.f32.tf32.tf32.f32 "
        "{%0,%1,%2,%3}, {%4,%5,%6,%7}, {%8,%9}, {%0,%1,%2,%3};"
        : "+f"(c[0]), "+f"(c[1]), "+f"(c[2]), "+f"(c[3])
        : "r"(a[0]), "r"(a[1]), "r"(a[2]), "r"(a[3]), "r"(b[0]), "r"(b[1]));
}
__device__ __forceinline__ uint32_t hi_bits(float x) {
    return __float_as_uint(x) & 0xFFFFE000u;
}
__device__ __forceinline__ uint32_t lo_tf32(float x, uint32_t h) {
    float lo = x - __uint_as_float(h);
    uint32_t r;
    asm("cvt.rna.tf32.f32 %0, %1;" : "=r"(r) : "f"(lo));
    return r;
}
__device__ __forceinline__ void split4(float4 v, uint4& h, uint4& l) {
    h.x = hi_bits(v.x); h.y = hi_bits(v.y); h.z = hi_bits(v.z); h.w = hi_bits(v.w);
    l.x = lo_tf32(v.x, h.x); l.y = lo_tf32(v.y, h.y);
    l.z = lo_tf32(v.z, h.z); l.w = lo_tf32(v.w, h.w);
}
__device__ __forceinline__ void lda(uint32_t* f, const uint32_t* S, int mb, int k0, int r, int q) {
    f[0] = S[(mb + r)     * STR + k0 + q];
    f[1] = S[(mb + r + 8) * STR + k0 + q];
    f[2] = S[(mb + r)     * STR + k0 + q + 4];
    f[3] = S[(mb + r + 8) * STR + k0 + q + 4];
}
__device__ __forceinline__ void ldb(uint32_t* f, const uint32_t* S, int nb, int k0, int r, int q) {
    f[0] = S[(nb + r) * STR + k0 + q];
    f[1] = S[(nb + r) * STR + k0 + q + 4];
}

// ---------------------------------------------------------------------------
// Scratch (device globals) — channel-last over the 56x56 domain
// ---------------------------------------------------------------------------
__device__ float g_q[BB * NQ * OUTC];
__device__ float g_k[BB * NQ * OUTC];
__device__ float g_v[BB * NQ * OUTC];

// ---------------------------------------------------------------------------
// Fused GEMM (Q / K / V block types), 3xTF32 mma.sync, DOUBLE-BUFFERED stages.
// Tile: 128(o) x 64(n); 8 warps 4(m)x2(n); warp 32x32.
// One __syncthreads per k-tile; next tile's LDG/STS overlap current MMAs.
// ---------------------------------------------------------------------------
#define STAGE_U32 ((2*128 + 2*64) * STR)       // 13824 u32 = 55296 B
#define G_SMEMB   (2 * STAGE_U32 * 4)          // 110592 B

__global__ __launch_bounds__(256, 2) void gemm_all(const float* __restrict__ fm,
                                                   const float* __restrict__ wq,
                                                   const float* __restrict__ wk,
                                                   const float* __restrict__ wv) {
    extern __shared__ uint32_t smu[];

    const int t  = threadIdx.x;
    const int id = blockIdx.x;

    const int type  = id / TPB;           // 0=Q, 1=K, 2=V
    const int local = id % TPB;
    const int ni_t = local % 49;
    const int rest = local / 49;
    const int o0 = (rest & 1) * 128;
    const int b  = rest >> 1;
    const int n0 = ni_t * 64;

    const float* W = (type == 0) ? wq : (type == 1) ? wk : wv;
    const float* X = fm + (size_t)b * (2 * CIN) * NQ + (type == 0 ? (size_t)CIN * NQ : 0);
    float* D = ((type == 0) ? g_q : (type == 1) ? g_k : g_v) + (size_t)b * NQ * OUTC;

    const int wid = t >> 5, l = t & 31;
    const int m0w = (wid & 3) * 32;
    const int n0w = (wid >> 2) * 32;
    const int r = l >> 2, q = l & 3;
    const int cc = t & 31, grp = t >> 5;

    float c[2][4][4];
#pragma unroll
    for (int mi = 0; mi < 2; mi++)
#pragma unroll
        for (int ni = 0; ni < 4; ni++)
#pragma unroll
            for (int e = 0; e < 4; e++) c[mi][ni][e] = 0.f;

    // staging registers
    float4 av[4], bv0, bv1;

    // ---- prologue: load + store k-tile 0 into stage 0 ----
#pragma unroll
    for (int i = 0; i < 4; i++) {
        int id2 = t + i * 256;
        int m = id2 >> 3, f = id2 & 7;
        av[i] = *(const float4*)&W[(size_t)(o0 + m) * CIN + f * 4];
    }
    {
        int nb = n0 + grp * 8;
        bv0 = *(const float4*)&X[(size_t)cc * NQ + nb];
        bv1 = *(const float4*)&X[(size_t)cc * NQ + nb + 4];
    }
    {
        uint32_t* AH = smu;
        uint32_t* AL = smu + 128 * STR;
        uint32_t* BH = smu + 2 * 128 * STR;
        uint32_t* BL = smu + 2 * 128 * STR + 64 * STR;
#pragma unroll
        for (int i = 0; i < 4; i++) {
            int id2 = t + i * 256;
            int m = id2 >> 3, f = id2 & 7;
            uint4 h, lo;
            split4(av[i], h, lo);
            *(uint4*)&AH[m * STR + f * 4] = h;
            *(uint4*)&AL[m * STR + f * 4] = lo;
        }
        uint4 h, lo;
        int nb = grp * 8;
        split4(bv0, h, lo);
        BH[(nb + 0) * STR + cc] = h.x;  BL[(nb + 0) * STR + cc] = lo.x;
        BH[(nb + 1) * STR + cc] = h.y;  BL[(nb + 1) * STR + cc] = lo.y;
        BH[(nb + 2) * STR + cc] = h.z;  BL[(nb + 2) * STR + cc] = lo.z;
        BH[(nb + 3) * STR + cc] = h.w;  BL[(nb + 3) * STR + cc] = lo.w;
        split4(bv1, h, lo);
        BH[(nb + 4) * STR + cc] = h.x;  BL[(nb + 4) * STR + cc] = lo.x;
        BH[(nb + 5) * STR + cc] = h.y;  BL[(nb + 5) * STR + cc] = lo.y;
        BH[(nb + 6) * STR + cc] = h.z;  BL[(nb + 6) * STR + cc] = lo.z;
        BH[(nb + 7) * STR + cc] = h.w;  BL[(nb + 7) * STR + cc] = lo.w;
    }
    __syncthreads();

#pragma unroll 1
    for (int kt = 0; kt < CIN / KT; kt++) {
        const int s = kt & 1;
        const uint32_t* AH = smu + s * STAGE_U32;
        const uint32_t* AL = AH + 128 * STR;
        const uint32_t* BH = AH + 2 * 128 * STR;
        const uint32_t* BL = AH + 2 * 128 * STR + 64 * STR;

        // issue next tile's gmem loads (land during this tile's MMAs)
        const bool more = (kt + 1) < CIN / KT;
        if (more) {
            const int c1 = (kt + 1) * KT;
#pragma unroll
            for (int i = 0; i < 4; i++) {
                int id2 = t + i * 256;
                int m = id2 >> 3, f = id2 & 7;
                av[i] = *(const float4*)&W[(size_t)(o0 + m) * CIN + c1 + f * 4];
            }
            int nb = n0 + grp * 8;
            bv0 = *(const float4*)&X[(size_t)(c1 + cc) * NQ + nb];
            bv1 = *(const float4*)&X[(size_t)(c1 + cc) * NQ + nb + 4];
        }

        // MMAs on current stage
#pragma unroll
        for (int ks = 0; ks < 4; ks++) {
            const int k0 = ks * 8;
            uint32_t ah[2][4], al[2][4];
            lda(ah[0], AH, m0w,      k0, r, q);
            lda(ah[1], AH, m0w + 16, k0, r, q);
            lda(al[0], AL, m0w,      k0, r, q);
            lda(al[1], AL, m0w + 16, k0, r, q);
#pragma unroll
            for (int ni = 0; ni < 4; ni++) {
                uint32_t bh[2], bl[2];
                ldb(bh, BH, n0w + ni * 8, k0, r, q);
                ldb(bl, BL, n0w + ni * 8, k0, r, q);
#pragma unroll
                for (int mi = 0; mi < 2; mi++) {
                    mma8(c[mi][ni], ah[mi], bh);
                    mma8(c[mi][ni], ah[mi], bl);
                    mma8(c[mi][ni], al[mi], bh);
                }
            }
        }

        // store next tile into the other stage (no race: other buffer)
        if (more) {
            uint32_t* AH2 = smu + (s ^ 1) * STAGE_U32;
            uint32_t* AL2 = AH2 + 128 * STR;
            uint32_t* BH2 = AH2 + 2 * 128 * STR;
            uint32_t* BL2 = AH2 + 2 * 128 * STR + 64 * STR;
#pragma unroll
            for (int i = 0; i < 4; i++) {
                int id2 = t + i * 256;
                int m = id2 >> 3, f = id2 & 7;
                uint4 h, lo;
                split4(av[i], h, lo);
                *(uint4*)&AH2[m * STR + f * 4] = h;
                *(uint4*)&AL2[m * STR + f * 4] = lo;
            }
            uint4 h, lo;
            int nb = grp * 8;
            split4(bv0, h, lo);
            BH2[(nb + 0) * STR + cc] = h.x;  BL2[(nb + 0) * STR + cc] = lo.x;
            BH2[(nb + 1) * STR + cc] = h.y;  BL2[(nb + 1) * STR + cc] = lo.y;
            BH2[(nb + 2) * STR + cc] = h.z;  BL2[(nb + 2) * STR + cc] = lo.z;
            BH2[(nb + 3) * STR + cc] = h.w;  BL2[(nb + 3) * STR + cc] = lo.w;
            split4(bv1, h, lo);
            BH2[(nb + 4) * STR + cc] = h.x;  BL2[(nb + 4) * STR + cc] = lo.x;
            BH2[(nb + 5) * STR + cc] = h.y;  BL2[(nb + 5) * STR + cc] = lo.y;
            BH2[(nb + 6) * STR + cc] = h.z;  BL2[(nb + 6) * STR + cc] = lo.z;
            BH2[(nb + 7) * STR + cc] = h.w;  BL2[(nb + 7) * STR + cc] = lo.w;
        }
        __syncthreads();
    }

    // Epilogue: transpose through SMEM -> coalesced channel-last stores
    float* Ct = (float*)smu;                 // [64 n][CSTR]
#pragma unroll
    for (int mi = 0; mi < 2; mi++)
#pragma unroll
        for (int ni = 0; ni < 4; ni++) {
            int m = m0w + mi * 16 + r;
            int n = n0w + ni * 8 + q * 2;
            Ct[(n)     * CSTR + m]     = c[mi][ni][0];
            Ct[(n + 1) * CSTR + m]     = c[mi][ni][1];
            Ct[(n)     * CSTR + m + 8] = c[mi][ni][2];
            Ct[(n + 1) * CSTR + m + 8] = c[mi][ni][3];
        }
    __syncthreads();
#pragma unroll
    for (int i = 0; i < 8; i++) {
        int id2 = t + i * 256;
        int n = id2 >> 5, f = id2 & 31;
        float4 v = *(float4*)&Ct[n * CSTR + f * 4];
        *(float4*)&D[(size_t)(n0 + n) * OUTC + o0 + f * 4] = v;
    }
}

// ---------------------------------------------------------------------------
// Attention (round-2 structure: two buffers, 128 thr, 2 threads/pixel)
// with zero-filled halo loads from the 56x56 domain.
// ---------------------------------------------------------------------------
#define TPIX   14
#define NPIX   (TPIX*TPIX)
#define SSTR   197
#define ATTN_SMEM (2 * 8 * SSTR * 16 + CG * KK * 4)   // 51328 B

__global__ __launch_bounds__(128) void attn_kernel(const float* __restrict__ relh,
                                                   const float* __restrict__ relw,
                                                   float* __restrict__ out) {
    extern __shared__ float4 smbuf[];
    float4* ks   = smbuf;                        // [8][SSTR]
    float4* vs   = smbuf + 8 * SSTR;             // [8][SSTR]
    float*  bias = (float*)(smbuf + 16 * SSTR);  // [32][7]

    const int b    = blockIdx.z;
    const int g    = blockIdx.y;
    const int tile = blockIdx.x;
    const int ty0  = (tile / 7) * 8;
    const int tx0  = (tile % 7) * 8;
    const int t    = threadIdx.x;
    const int p    = t >> 1;
    const int half = t & 1;

    const float* rel = (g < 4) ? (relh + (size_t)g * CG * KK)
                               : (relw + (size_t)(g - 4) * CG * KK);
    for (int i = t; i < CG * KK; i += 128) bias[i] = rel[i];

    for (int idx = t; idx < NPIX * 8; idx += 128) {
        int c4 = idx & 7;
        int pp = idx >> 3;
        int py = pp / TPIX, px = pp - py * TPIX;
        int yy = ty0 + py - PADV, xx = tx0 + px - PADV;
        float4 kv = make_float4(0.f, 0.f, 0.f, 0.f);
        float4 vv = make_float4(0.f, 0.f, 0.f, 0.f);
        if (yy >= 0 && yy < HH && xx >= 0 && xx < WW) {
            size_t gbase = ((size_t)b * NQ + yy * WW + xx) * OUTC + g * CG;
            kv = *((const float4*)&g_k[gbase] + c4);
            vv = *((const float4*)&g_v[gbase] + c4);
        }
        ks[c4 * SSTR + pp] = kv;
        vs[c4 * SSTR + pp] = vv;
    }
    __syncthreads();

    const int lty = p >> 3, ltx = p & 7;
    const int h = ty0 + lty, w = tx0 + ltx;
    const int pbase = lty * TPIX + ltx;
    const int c4b = half * 4;

    float qf[16];
    {
        const float4* qp = (const float4*)&g_q[((size_t)b * NQ + h * WW + w) * OUTC + g * CG];
#pragma unroll
        for (int c4 = 0; c4 < 4; c4++) {
            float4 v = qp[c4b + c4];
            qf[c4 * 4 + 0] = v.x; qf[c4 * 4 + 1] = v.y;
            qf[c4 * 4 + 2] = v.z; qf[c4 * 4 + 3] = v.w;
        }
    }

    float db[KK];
#pragma unroll
    for (int i = 0; i < KK; i++) {
        float s = 0.f;
#pragma unroll
        for (int c = 0; c < 16; c++) s += qf[c] * bias[(half * 16 + c) * KK + i];
        db[i] = s;
    }
#pragma unroll
    for (int i = 0; i < KK; i++) db[i] += __shfl_xor_sync(0xffffffffu, db[i], 1);

    float lg[KK * KK];
#pragma unroll
    for (int n = 0; n < KK * KK; n++) {
        const int i = n / KK, j = n % KK;
        const int pp = pbase + i * TPIX + j;
        float s = 0.f;
#pragma unroll
        for (int c4 = 0; c4 < 4; c4++) {
            float4 kv = ks[(c4b + c4) * SSTR + pp];
            s += qf[c4 * 4 + 0] * kv.x + qf[c4 * 4 + 1] * kv.y
               + qf[c4 * 4 + 2] * kv.z + qf[c4 * 4 + 3] * kv.w;
        }
        lg[n] = s;
    }
#pragma unroll
    for (int n = 0; n < KK * KK; n++)
        lg[n] += __shfl_xor_sync(0xffffffffu, lg[n], 1);
#pragma unroll
    for (int n = 0; n < KK * KK; n++)
        lg[n] += (g < 4) ? db[n / KK] : db[n % KK];

    float mx = lg[0];
#pragma unroll
    for (int n = 1; n < KK * KK; n++) mx = fmaxf(mx, lg[n]);
    float sum = 0.f;
#pragma unroll
    for (int n = 0; n < KK * KK; n++) { lg[n] = __expf(lg[n] - mx); sum += lg[n]; }
    float inv = 1.f / sum;
#pragma unroll
    for (int n = 0; n < KK * KK; n++) lg[n] *= inv;

#pragma unroll
    for (int c4 = 0; c4 < 4; c4++) {
        float4 acc = make_float4(0.f, 0.f, 0.f, 0.f);
#pragma unroll
        for (int n = 0; n < KK * KK; n++) {
            const int pp = pbase + (n / KK) * TPIX + (n % KK);
            float4 vv = vs[(c4b + c4) * SSTR + pp];
            acc.x += lg[n] * vv.x;
            acc.y += lg[n] * vv.y;
            acc.z += lg[n] * vv.z;
            acc.w += lg[n] * vv.w;
        }
        size_t base = ((size_t)(b * OUTC + g * CG + (c4b + c4) * 4)) * NQ + h * WW + w;
        out[base]          = acc.x;
        out[base + NQ]     = acc.y;
        out[base + 2 * NQ] = acc.z;
        out[base + 3 * NQ] = acc.w;
    }
}

// ---------------------------------------------------------------------------
// Launch
// ---------------------------------------------------------------------------
extern "C" void kernel_launch(void* const* d_in, const int* in_sizes, int n_in,
                              void* d_out, int out_size) {
    const float* fm = (const float*)d_in[0];
    const float* wq = (const float*)d_in[1];
    const float* wk = (const float*)d_in[2];
    const float* wv = (const float*)d_in[3];
    const float* rh = (const float*)d_in[4];
    const float* rw = (const float*)d_in[5];
    float* out = (float*)d_out;

    cudaFuncSetAttribute(attn_kernel, cudaFuncAttributeMaxDynamicSharedMemorySize, ATTN_SMEM);
    cudaFuncSetAttribute(gemm_all,    cudaFuncAttributeMaxDynamicSharedMemorySize, G_SMEMB);

    gemm_all<<<TOT_TILES, 256, G_SMEMB>>>(fm, wq, wk, wv);
    attn_kernel<<<dim3(49, GRP, BB), 128, ATTN_SMEM>>>(rh, rw, out);
}

// round 9
// speedup vs baseline: 1.5395x; 1.1065x over previous
#include <cuda_runtime.h>
#include <cstdint>

// ---------------------------------------------------------------------------
// Problem constants
// ---------------------------------------------------------------------------
#define BB    2
#define CIN   256
#define HH    56
#define WW    56
#define OUTC  256
#define KK    7
#define PADV  3
#define GRP   8
#define CG    32
#define NQ    (HH*WW)     // 3136 = 49*64

#define KT    32          // k-tile (fp32 channels per stage)
#define STR2  20          // SMEM u32 stride per row (16 words + pad; r*20%32 all mult-of-4)
#define CSTR  132         // epilogue transpose stride

#define TPB   196
#define TOT_TILES (3*TPB) // 588

// ---------------------------------------------------------------------------
// MMA helpers (portable sm_80+ PTX)
// ---------------------------------------------------------------------------
__device__ __forceinline__ void mma16(float* c, const uint32_t* a, const uint32_t* b) {
    asm volatile("mma.sync.aligned.m16n8k16.row.col.f32.bf16.bf16.f32 "
        "{%0,%1,%2,%3}, {%4,%5,%6,%7}, {%8,%9}, {%0,%1,%2,%3};"
        : "+f"(c[0]), "+f"(c[1]), "+f"(c[2]), "+f"(c[3])
        : "r"(a[0]), "r"(a[1]), "r"(a[2]), "r"(a[3]), "r"(b[0]), "r"(b[1]));
}
// pack two floats to bf16x2: result.hi = bf16(hi_f), result.lo = bf16(lo_f)
__device__ __forceinline__ uint32_t pk_bf2(float hi_f, float lo_f) {
    uint32_t r;
    asm("cvt.rn.bf16x2.f32 %0, %1, %2;" : "=r"(r) : "f"(hi_f), "f"(lo_f));
    return r;
}
__device__ __forceinline__ float bf_lo_f(uint32_t w) { return __uint_as_float(w << 16); }
__device__ __forceinline__ float bf_hi_f(uint32_t w) { return __uint_as_float(w & 0xFFFF0000u); }

// A fragment (m16 k16) base (mb, word kw0); r=lane>>2, q=lane&3
__device__ __forceinline__ void lda(uint32_t* f, const uint32_t* S, int mb, int kw0, int r, int q) {
    f[0] = S[(mb + r)     * STR2 + kw0 + q];
    f[1] = S[(mb + r + 8) * STR2 + kw0 + q];
    f[2] = S[(mb + r)     * STR2 + kw0 + q + 4];
    f[3] = S[(mb + r + 8) * STR2 + kw0 + q + 4];
}
// B fragment (n8 k16)
__device__ __forceinline__ void ldb(uint32_t* f, const uint32_t* S, int nb, int kw0, int r, int q) {
    f[0] = S[(nb + r) * STR2 + kw0 + q];
    f[1] = S[(nb + r) * STR2 + kw0 + q + 4];
}

// ---------------------------------------------------------------------------
// Scratch (device globals) — channel-last over the 56x56 domain
// ---------------------------------------------------------------------------
__device__ float g_q[BB * NQ * OUTC];
__device__ float g_k[BB * NQ * OUTC];
__device__ float g_v[BB * NQ * OUTC];

// ---------------------------------------------------------------------------
// Fused GEMM (Q / K / V block types), 3xBF16 m16n8k16, double-buffered.
// Tile: 128(o) x 64(n); 8 warps 4(m)x2(n); warp 32x32.
// SMEM stage: AH/AL [128][20] + BH/BL [64][20] u32 = 30720 B; 2 stages.
// ---------------------------------------------------------------------------
#define A_W   (128 * STR2)             // 2560 u32
#define B_W   (64 * STR2)              // 1280 u32
#define STAGE_U32 (2*A_W + 2*B_W)      // 7680 u32 = 30720 B
#define G_SMEMB   (2 * STAGE_U32 * 4)  // 61440 B

__global__ __launch_bounds__(256, 2) void gemm_all(const float* __restrict__ fm,
                                                   const float* __restrict__ wq,
                                                   const float* __restrict__ wk,
                                                   const float* __restrict__ wv) {
    extern __shared__ uint32_t smu[];

    const int t  = threadIdx.x;
    const int id = blockIdx.x;

    const int type  = id / TPB;           // 0=Q, 1=K, 2=V
    const int local = id % TPB;
    const int ni_t = local % 49;
    const int rest = local / 49;
    const int o0 = (rest & 1) * 128;
    const int b  = rest >> 1;
    const int n0 = ni_t * 64;

    const float* W = (type == 0) ? wq : (type == 1) ? wk : wv;
    const float* X = fm + (size_t)b * (2 * CIN) * NQ + (type == 0 ? (size_t)CIN * NQ : 0);
    float* D = ((type == 0) ? g_q : (type == 1) ? g_k : g_v) + (size_t)b * NQ * OUTC;

    const int wid = t >> 5, l = t & 31;
    const int m0w = (wid & 3) * 32;
    const int n0w = (wid >> 2) * 32;
    const int r = l >> 2, q = l & 3;
    const int cc = t & 31, grp = t >> 5;           // B-load role
    const bool ceven = ((cc & 1) == 0);

    float c[2][4][4];
#pragma unroll
    for (int mi = 0; mi < 2; mi++)
#pragma unroll
        for (int ni = 0; ni < 4; ni++)
#pragma unroll
            for (int e = 0; e < 4; e++) c[mi][ni][e] = 0.f;

    float4 av[4];
    float  bvals[8];

    // ---- helper lambdas as macros via code blocks ----
    // stage store: writes av/bvals (already loaded) into stage s
#define STORE_STAGE(Sbase)                                                        \
    {                                                                             \
        uint32_t* AH = (Sbase);                                                   \
        uint32_t* AL = (Sbase) + A_W;                                             \
        uint32_t* BHs = (Sbase) + 2 * A_W;                                        \
        uint32_t* BLs = (Sbase) + 2 * A_W + B_W;                                  \
        _Pragma("unroll")                                                         \
        for (int i = 0; i < 4; i++) {                                             \
            int id2 = t + i * 256;                                                \
            int m = id2 >> 3, f = id2 & 7;                                        \
            float4 v = av[i];                                                     \
            uint32_t w0 = pk_bf2(v.y, v.x);                                       \
            uint32_t w1 = pk_bf2(v.w, v.z);                                       \
            float l0 = v.x - bf_lo_f(w0), l1 = v.y - bf_hi_f(w0);                 \
            float l2 = v.z - bf_lo_f(w1), l3 = v.w - bf_hi_f(w1);                 \
            uint32_t u0 = pk_bf2(l1, l0);                                         \
            uint32_t u1 = pk_bf2(l3, l2);                                         \
            *(uint2*)&AH[m * STR2 + f * 2] = make_uint2(w0, w1);                  \
            *(uint2*)&AL[m * STR2 + f * 2] = make_uint2(u0, u1);                  \
        }                                                                         \
        _Pragma("unroll")                                                         \
        for (int j = 0; j < 8; j++) {                                             \
            float v  = bvals[j];                                                  \
            float ov = __shfl_xor_sync(0xffffffffu, v, 1);                        \
            float ev = ceven ? v : ov;                                            \
            float od = ceven ? ov : v;                                            \
            uint32_t wh = pk_bf2(od, ev);                                         \
            float selfhi = ceven ? bf_lo_f(wh) : bf_hi_f(wh);                     \
            float rl  = v - selfhi;                                               \
            float orl = __shfl_xor_sync(0xffffffffu, rl, 1);                      \
            float evl = ceven ? rl : orl;                                         \
            float odl = ceven ? orl : rl;                                         \
            uint32_t wl = pk_bf2(odl, evl);                                       \
            if (ceven) {                                                          \
                BHs[(grp * 8 + j) * STR2 + (cc >> 1)] = wh;                       \
                BLs[(grp * 8 + j) * STR2 + (cc >> 1)] = wl;                       \
            }                                                                     \
        }                                                                         \
    }

    // ---- prologue: load + store k-tile 0 into stage 0 ----
#pragma unroll
    for (int i = 0; i < 4; i++) {
        int id2 = t + i * 256;
        int m = id2 >> 3, f = id2 & 7;
        av[i] = *(const float4*)&W[(size_t)(o0 + m) * CIN + f * 4];
    }
    {
        int nb = n0 + grp * 8;
        float4 b0 = *(const float4*)&X[(size_t)cc * NQ + nb];
        float4 b1 = *(const float4*)&X[(size_t)cc * NQ + nb + 4];
        bvals[0] = b0.x; bvals[1] = b0.y; bvals[2] = b0.z; bvals[3] = b0.w;
        bvals[4] = b1.x; bvals[5] = b1.y; bvals[6] = b1.z; bvals[7] = b1.w;
    }
    STORE_STAGE(smu);
    __syncthreads();

#pragma unroll 1
    for (int kt = 0; kt < CIN / KT; kt++) {
        const int s = kt & 1;
        const uint32_t* AH = smu + s * STAGE_U32;
        const uint32_t* AL = AH + A_W;
        const uint32_t* BH = AH + 2 * A_W;
        const uint32_t* BL = AH + 2 * A_W + B_W;

        const bool more = (kt + 1) < CIN / KT;
        if (more) {
            const int c1 = (kt + 1) * KT;
#pragma unroll
            for (int i = 0; i < 4; i++) {
                int id2 = t + i * 256;
                int m = id2 >> 3, f = id2 & 7;
                av[i] = *(const float4*)&W[(size_t)(o0 + m) * CIN + c1 + f * 4];
            }
            int nb = n0 + grp * 8;
            float4 b0 = *(const float4*)&X[(size_t)(c1 + cc) * NQ + nb];
            float4 b1 = *(const float4*)&X[(size_t)(c1 + cc) * NQ + nb + 4];
            bvals[0] = b0.x; bvals[1] = b0.y; bvals[2] = b0.z; bvals[3] = b0.w;
            bvals[4] = b1.x; bvals[5] = b1.y; bvals[6] = b1.z; bvals[7] = b1.w;
        }

        // MMAs on current stage: 2 k16-steps
#pragma unroll
        for (int ks = 0; ks < 2; ks++) {
            const int kw0 = ks * 8;
            uint32_t ah[2][4], al2[2][4];
            lda(ah[0],  AH, m0w,      kw0, r, q);
            lda(ah[1],  AH, m0w + 16, kw0, r, q);
            lda(al2[0], AL, m0w,      kw0, r, q);
            lda(al2[1], AL, m0w + 16, kw0, r, q);
#pragma unroll
            for (int ni = 0; ni < 4; ni++) {
                uint32_t bh[2], bl[2];
                ldb(bh, BH, n0w + ni * 8, kw0, r, q);
                ldb(bl, BL, n0w + ni * 8, kw0, r, q);
#pragma unroll
                for (int mi = 0; mi < 2; mi++) {
                    mma16(c[mi][ni], ah[mi],  bh);
                    mma16(c[mi][ni], ah[mi],  bl);
                    mma16(c[mi][ni], al2[mi], bh);
                }
            }
        }

        if (more) {
            STORE_STAGE(smu + (s ^ 1) * STAGE_U32);
        }
        __syncthreads();
    }

    // Epilogue: transpose through SMEM -> coalesced channel-last stores
    float* Ct = (float*)smu;                 // [64 n][CSTR]
#pragma unroll
    for (int mi = 0; mi < 2; mi++)
#pragma unroll
        for (int ni = 0; ni < 4; ni++) {
            int m = m0w + mi * 16 + r;
            int n = n0w + ni * 8 + q * 2;
            Ct[(n)     * CSTR + m]     = c[mi][ni][0];
            Ct[(n + 1) * CSTR + m]     = c[mi][ni][1];
            Ct[(n)     * CSTR + m + 8] = c[mi][ni][2];
            Ct[(n + 1) * CSTR + m + 8] = c[mi][ni][3];
        }
    __syncthreads();
#pragma unroll
    for (int i = 0; i < 8; i++) {
        int id2 = t + i * 256;
        int n = id2 >> 5, f = id2 & 31;
        float4 v = *(float4*)&Ct[n * CSTR + f * 4];
        *(float4*)&D[(size_t)(n0 + n) * OUTC + o0 + f * 4] = v;
    }
}

// ---------------------------------------------------------------------------
// Attention (round-8 version, unchanged)
// ---------------------------------------------------------------------------
#define TPIX   14
#define NPIX   (TPIX*TPIX)
#define SSTR   197
#define ATTN_SMEM (2 * 8 * SSTR * 16 + CG * KK * 4)   // 51328 B

__global__ __launch_bounds__(128) void attn_kernel(const float* __restrict__ relh,
                                                   const float* __restrict__ relw,
                                                   float* __restrict__ out) {
    extern __shared__ float4 smbuf[];
    float4* ks   = smbuf;
    float4* vs   = smbuf + 8 * SSTR;
    float*  bias = (float*)(smbuf + 16 * SSTR);

    const int b    = blockIdx.z;
    const int g    = blockIdx.y;
    const int tile = blockIdx.x;
    const int ty0  = (tile / 7) * 8;
    const int tx0  = (tile % 7) * 8;
    const int t    = threadIdx.x;
    const int p    = t >> 1;
    const int half = t & 1;

    const float* rel = (g < 4) ? (relh + (size_t)g * CG * KK)
                               : (relw + (size_t)(g - 4) * CG * KK);
    for (int i = t; i < CG * KK; i += 128) bias[i] = rel[i];

    for (int idx = t; idx < NPIX * 8; idx += 128) {
        int c4 = idx & 7;
        int pp = idx >> 3;
        int py = pp / TPIX, px = pp - py * TPIX;
        int yy = ty0 + py - PADV, xx = tx0 + px - PADV;
        float4 kv = make_float4(0.f, 0.f, 0.f, 0.f);
        float4 vv = make_float4(0.f, 0.f, 0.f, 0.f);
        if (yy >= 0 && yy < HH && xx >= 0 && xx < WW) {
            size_t gbase = ((size_t)b * NQ + yy * WW + xx) * OUTC + g * CG;
            kv = *((const float4*)&g_k[gbase] + c4);
            vv = *((const float4*)&g_v[gbase] + c4);
        }
        ks[c4 * SSTR + pp] = kv;
        vs[c4 * SSTR + pp] = vv;
    }
    __syncthreads();

    const int lty = p >> 3, ltx = p & 7;
    const int h = ty0 + lty, w = tx0 + ltx;
    const int pbase = lty * TPIX + ltx;
    const int c4b = half * 4;

    float qf[16];
    {
        const float4* qp = (const float4*)&g_q[((size_t)b * NQ + h * WW + w) * OUTC + g * CG];
#pragma unroll
        for (int c4 = 0; c4 < 4; c4++) {
            float4 v = qp[c4b + c4];
            qf[c4 * 4 + 0] = v.x; qf[c4 * 4 + 1] = v.y;
            qf[c4 * 4 + 2] = v.z; qf[c4 * 4 + 3] = v.w;
        }
    }

    float db[KK];
#pragma unroll
    for (int i = 0; i < KK; i++) {
        float s = 0.f;
#pragma unroll
        for (int c = 0; c < 16; c++) s += qf[c] * bias[(half * 16 + c) * KK + i];
        db[i] = s;
    }
#pragma unroll
    for (int i = 0; i < KK; i++) db[i] += __shfl_xor_sync(0xffffffffu, db[i], 1);

    float lg[KK * KK];
#pragma unroll
    for (int n = 0; n < KK * KK; n++) {
        const int i = n / KK, j = n % KK;
        const int pp = pbase + i * TPIX + j;
        float s = 0.f;
#pragma unroll
        for (int c4 = 0; c4 < 4; c4++) {
            float4 kv = ks[(c4b + c4) * SSTR + pp];
            s += qf[c4 * 4 + 0] * kv.x + qf[c4 * 4 + 1] * kv.y
               + qf[c4 * 4 + 2] * kv.z + qf[c4 * 4 + 3] * kv.w;
        }
        lg[n] = s;
    }
#pragma unroll
    for (int n = 0; n < KK * KK; n++)
        lg[n] += __shfl_xor_sync(0xffffffffu, lg[n], 1);
#pragma unroll
    for (int n = 0; n < KK * KK; n++)
        lg[n] += (g < 4) ? db[n / KK] : db[n % KK];

    float mx = lg[0];
#pragma unroll
    for (int n = 1; n < KK * KK; n++) mx = fmaxf(mx, lg[n]);
    float sum = 0.f;
#pragma unroll
    for (int n = 0; n < KK * KK; n++) { lg[n] = __expf(lg[n] - mx); sum += lg[n]; }
    float inv = 1.f / sum;
#pragma unroll
    for (int n = 0; n < KK * KK; n++) lg[n] *= inv;

#pragma unroll
    for (int c4 = 0; c4 < 4; c4++) {
        float4 acc = make_float4(0.f, 0.f, 0.f, 0.f);
#pragma unroll
        for (int n = 0; n < KK * KK; n++) {
            const int pp = pbase + (n / KK) * TPIX + (n % KK);
            float4 vv = vs[(c4b + c4) * SSTR + pp];
            acc.x += lg[n] * vv.x;
            acc.y += lg[n] * vv.y;
            acc.z += lg[n] * vv.z;
            acc.w += lg[n] * vv.w;
        }
        size_t base = ((size_t)(b * OUTC + g * CG + (c4b + c4) * 4)) * NQ + h * WW + w;
        out[base]          = acc.x;
        out[base + NQ]     = acc.y;
        out[base + 2 * NQ] = acc.z;
        out[base + 3 * NQ] = acc.w;
    }
}

// ---------------------------------------------------------------------------
// Launch
// ---------------------------------------------------------------------------
extern "C" void kernel_launch(void* const* d_in, const int* in_sizes, int n_in,
                              void* d_out, int out_size) {
    const float* fm = (const float*)d_in[0];
    const float* wq = (const float*)d_in[1];
    const float* wk = (const float*)d_in[2];
    const float* wv = (const float*)d_in[3];
    const float* rh = (const float*)d_in[4];
    const float* rw = (const float*)d_in[5];
    float* out = (float*)d_out;

    cudaFuncSetAttribute(attn_kernel, cudaFuncAttributeMaxDynamicSharedMemorySize, ATTN_SMEM);
    cudaFuncSetAttribute(gemm_all,    cudaFuncAttributeMaxDynamicSharedMemorySize, G_SMEMB);

    gemm_all<<<TOT_TILES, 256, G_SMEMB>>>(fm, wq, wk, wv);
    attn_kernel<<<dim3(49, GRP, BB), 128, ATTN_SMEM>>>(rh, rw, out);
}

// round 10
// speedup vs baseline: 1.5475x; 1.0052x over previous
#include <cuda_runtime.h>
#include <cstdint>

// ---------------------------------------------------------------------------
// Problem constants
// ---------------------------------------------------------------------------
#define BB    2
#define CIN   256
#define HH    56
#define WW    56
#define OUTC  256
#define KK    7
#define PADV  3
#define GRP   8
#define CG    32
#define NQ    (HH*WW)     // 3136 = 49*64

#define KT    32          // fp32 channels per k-tile (= 16 bf16x2 words)
#define STR2  20          // SMEM u32 stride per row (16 words + 4 pad)
#define CSTR  132         // epilogue transpose stride

#define TPB   196
#define TOT_TILES (3*TPB) // 588

// ---------------------------------------------------------------------------
// helpers (portable sm_80+ PTX)
// ---------------------------------------------------------------------------
__device__ __forceinline__ void mma16(float* c, const uint32_t* a, const uint32_t* b) {
    asm volatile("mma.sync.aligned.m16n8k16.row.col.f32.bf16.bf16.f32 "
        "{%0,%1,%2,%3}, {%4,%5,%6,%7}, {%8,%9}, {%0,%1,%2,%3};"
        : "+f"(c[0]), "+f"(c[1]), "+f"(c[2]), "+f"(c[3])
        : "r"(a[0]), "r"(a[1]), "r"(a[2]), "r"(a[3]), "r"(b[0]), "r"(b[1]));
}
__device__ __forceinline__ uint32_t pk_bf2(float hi_f, float lo_f) {
    uint32_t r;
    asm("cvt.rn.bf16x2.f32 %0, %1, %2;" : "=r"(r) : "f"(hi_f), "f"(lo_f));
    return r;
}
__device__ __forceinline__ float bf_lo_f(uint32_t w) { return __uint_as_float(w << 16); }
__device__ __forceinline__ float bf_hi_f(uint32_t w) { return __uint_as_float(w & 0xFFFF0000u); }

__device__ __forceinline__ uint32_t smem_u32(const void* p) {
    return (uint32_t)__cvta_generic_to_shared(p);
}
__device__ __forceinline__ void cpa16(uint32_t dst, const void* src) {
    asm volatile("cp.async.ca.shared.global [%0], [%1], 16;" :: "r"(dst), "l"(src));
}
#define CPA_COMMIT() asm volatile("cp.async.commit_group;" ::: "memory")
#define CPA_WAIT0()  asm volatile("cp.async.wait_group 0;"  ::: "memory")

// ldmatrix: A fragment (m16k16) from [row][k-word] layout, byte-base abase
__device__ __forceinline__ void ldsmA(uint32_t* f, uint32_t abase, int mb, int kw0, int l) {
    uint32_t addr = abase + (uint32_t)(((mb + (l & 15)) * STR2 + kw0 + ((l >> 2) & 4)) * 4);
    asm volatile("ldmatrix.sync.aligned.m8n8.x4.shared.b16 {%0,%1,%2,%3}, [%4];"
        : "=r"(f[0]), "=r"(f[1]), "=r"(f[2]), "=r"(f[3]) : "r"(addr));
}
// ldmatrix: B fragment (n8k16)
__device__ __forceinline__ void ldsmB(uint32_t* f, uint32_t bbase, int nb, int kw0, int l) {
    uint32_t addr = bbase + (uint32_t)(((nb + (l & 7)) * STR2 + kw0 + ((l >> 1) & 4)) * 4);
    asm volatile("ldmatrix.sync.aligned.m8n8.x2.shared.b16 {%0,%1}, [%2];"
        : "=r"(f[0]), "=r"(f[1]) : "r"(addr));
}

// ---------------------------------------------------------------------------
// Scratch (device globals)
// ---------------------------------------------------------------------------
__device__ float g_q[BB * NQ * OUTC];
__device__ float g_k[BB * NQ * OUTC];
__device__ float g_v[BB * NQ * OUTC];
__device__ uint32_t g_wh[3 * 256 * 128];   // bf16x2 hi words: [type][o][kw]
__device__ uint32_t g_wl[3 * 256 * 128];   // bf16x2 lo words

// ---------------------------------------------------------------------------
// 0) Weight prep: fp32 -> bf16 hi/lo packed words (once, ~2us)
// ---------------------------------------------------------------------------
__global__ void prep_w(const float* __restrict__ wq, const float* __restrict__ wk,
                       const float* __restrict__ wv) {
    int idx = blockIdx.x * blockDim.x + threadIdx.x;
    if (idx >= 3 * 256 * 128) return;
    int type = idx / (256 * 128);
    int rem  = idx % (256 * 128);
    const float* W = (type == 0) ? wq : (type == 1) ? wk : wv;
    float2 v = *(const float2*)&W[(size_t)rem * 2];
    uint32_t wh = pk_bf2(v.y, v.x);
    float l0 = v.x - bf_lo_f(wh), l1 = v.y - bf_hi_f(wh);
    g_wh[idx] = wh;
    g_wl[idx] = pk_bf2(l1, l0);
}

// ---------------------------------------------------------------------------
// Fused GEMM: 3xBF16 m16n8k16, cp.async A-tiles, ldmatrix fragments,
// double-buffered. Tile 128(o) x 64(n); 8 warps 4x2; warp 32x32.
// ---------------------------------------------------------------------------
#define A_W   (128 * STR2)             // 2560 u32 (one of AH/AL)
#define B_W   (64 * STR2)              // 1280 u32
#define STAGE_U32 (2*A_W + 2*B_W)      // 7680 u32 = 30720 B
#define G_SMEMB   (2 * STAGE_U32 * 4)  // 61440 B

__global__ __launch_bounds__(256, 2) void gemm_all(const float* __restrict__ fm) {
    extern __shared__ uint32_t smu[];
    const uint32_t sbase = smem_u32(smu);

    const int t  = threadIdx.x;
    const int id = blockIdx.x;

    const int type  = id / TPB;           // 0=Q, 1=K, 2=V
    const int local = id % TPB;
    const int ni_t = local % 49;
    const int rest = local / 49;
    const int o0 = (rest & 1) * 128;
    const int b  = rest >> 1;
    const int n0 = ni_t * 64;

    const float* X = fm + (size_t)b * (2 * CIN) * NQ + (type == 0 ? (size_t)CIN * NQ : 0);
    float* D = ((type == 0) ? g_q : (type == 1) ? g_k : g_v) + (size_t)b * NQ * OUTC;
    const uint32_t* WHrow = g_wh + ((size_t)type * 256 + o0) * 128;
    const uint32_t* WLrow = g_wl + ((size_t)type * 256 + o0) * 128;

    const int wid = t >> 5, l = t & 31;
    const int m0w = (wid & 3) * 32;
    const int n0w = (wid >> 2) * 32;
    const int cc = t & 31, grp = t >> 5;           // B-load role
    const bool ceven = ((cc & 1) == 0);
    const int am = t >> 2, af = t & 3;             // A cp.async role (rows 0..63 / 64..127)

    float c[2][4][4];
#pragma unroll
    for (int mi = 0; mi < 2; mi++)
#pragma unroll
        for (int ni = 0; ni < 4; ni++)
#pragma unroll
            for (int e = 0; e < 4; e++) c[mi][ni][e] = 0.f;

    float bvals[8];

    // A cp.async issue for k-tile `ktile` into stage byte-base stb
#define CPA_A(stb, ktile)                                                     \
    {                                                                         \
        int kw = (ktile) * 16;                                                \
        _Pragma("unroll")                                                     \
        for (int i = 0; i < 2; i++) {                                         \
            int m = am + i * 64;                                              \
            uint32_t doff = (uint32_t)((m * STR2 + af * 4) * 4);              \
            cpa16((stb) + doff,         WHrow + (size_t)m * 128 + kw + af*4); \
            cpa16((stb) + A_W*4 + doff, WLrow + (size_t)m * 128 + kw + af*4); \
        }                                                                     \
        CPA_COMMIT();                                                         \
    }

    // B load (fp32) for k-tile into bvals
#define LDG_B(ktile)                                                          \
    {                                                                         \
        const int c1 = (ktile) * KT;                                          \
        int nb = n0 + grp * 8;                                                \
        float4 b0 = *(const float4*)&X[(size_t)(c1 + cc) * NQ + nb];          \
        float4 b1 = *(const float4*)&X[(size_t)(c1 + cc) * NQ + nb + 4];      \
        bvals[0] = b0.x; bvals[1] = b0.y; bvals[2] = b0.z; bvals[3] = b0.w;   \
        bvals[4] = b1.x; bvals[5] = b1.y; bvals[6] = b1.z; bvals[7] = b1.w;   \
    }

    // B convert + store into stage word-base Sptr
#define STORE_B(Sptr)                                                         \
    {                                                                         \
        uint32_t* BHs = (Sptr) + 2 * A_W;                                     \
        uint32_t* BLs = (Sptr) + 2 * A_W + B_W;                               \
        _Pragma("unroll")                                                     \
        for (int j = 0; j < 8; j++) {                                         \
            float v  = bvals[j];                                              \
            float ov = __shfl_xor_sync(0xffffffffu, v, 1);                    \
            float ev = ceven ? v : ov;                                        \
            float od = ceven ? ov : v;                                        \
            uint32_t wh = pk_bf2(od, ev);                                     \
            float selfhi = ceven ? bf_lo_f(wh) : bf_hi_f(wh);                 \
            float rl  = v - selfhi;                                           \
            float orl = __shfl_xor_sync(0xffffffffu, rl, 1);                  \
            float evl = ceven ? rl : orl;                                     \
            float odl = ceven ? orl : rl;                                     \
            uint32_t wl = pk_bf2(odl, evl);                                   \
            if (ceven) {                                                      \
                BHs[(grp * 8 + j) * STR2 + (cc >> 1)] = wh;                   \
                BLs[(grp * 8 + j) * STR2 + (cc >> 1)] = wl;                   \
            }                                                                 \
        }                                                                     \
    }

    // ---- prologue: k-tile 0 into stage 0 ----
    CPA_A(sbase, 0);
    LDG_B(0);
    STORE_B(smu);
    CPA_WAIT0();
    __syncthreads();

#pragma unroll 1
    for (int kt = 0; kt < CIN / KT; kt++) {
        const int s = kt & 1;
        const uint32_t stb  = sbase + (uint32_t)(s * STAGE_U32 * 4);
        const uint32_t aH = stb;
        const uint32_t aL = stb + A_W * 4;
        const uint32_t bH = stb + 2 * A_W * 4;
        const uint32_t bL = stb + (2 * A_W + B_W) * 4;

        const bool more = (kt + 1) < CIN / KT;
        if (more) {
            const uint32_t st2 = sbase + (uint32_t)((s ^ 1) * STAGE_U32 * 4);
            CPA_A(st2, kt + 1);
            LDG_B(kt + 1);
        }

        // MMAs on current stage: 2 k16-steps, ldmatrix fragments
#pragma unroll
        for (int ks = 0; ks < 2; ks++) {
            const int kw0 = ks * 8;
            uint32_t ah0[4], ah1[4], al0[4], al1[4];
            ldsmA(ah0, aH, m0w,      kw0, l);
            ldsmA(ah1, aH, m0w + 16, kw0, l);
            ldsmA(al0, aL, m0w,      kw0, l);
            ldsmA(al1, aL, m0w + 16, kw0, l);
#pragma unroll
            for (int ni = 0; ni < 4; ni++) {
                uint32_t bh[2], bl[2];
                ldsmB(bh, bH, n0w + ni * 8, kw0, l);
                ldsmB(bl, bL, n0w + ni * 8, kw0, l);
                mma16(c[0][ni], ah0, bh);
                mma16(c[0][ni], ah0, bl);
                mma16(c[0][ni], al0, bh);
                mma16(c[1][ni], ah1, bh);
                mma16(c[1][ni], ah1, bl);
                mma16(c[1][ni], al1, bh);
            }
        }

        if (more) {
            uint32_t* st2w = smu + (s ^ 1) * STAGE_U32;
            STORE_B(st2w);
        }
        CPA_WAIT0();
        __syncthreads();
    }

    // Epilogue: transpose through SMEM -> coalesced channel-last stores
    const int r = l >> 2, q = l & 3;
    float* Ct = (float*)smu;                 // [64 n][CSTR]
#pragma unroll
    for (int mi = 0; mi < 2; mi++)
#pragma unroll
        for (int ni = 0; ni < 4; ni++) {
            int m = m0w + mi * 16 + r;
            int n = n0w + ni * 8 + q * 2;
            Ct[(n)     * CSTR + m]     = c[mi][ni][0];
            Ct[(n + 1) * CSTR + m]     = c[mi][ni][1];
            Ct[(n)     * CSTR + m + 8] = c[mi][ni][2];
            Ct[(n + 1) * CSTR + m + 8] = c[mi][ni][3];
        }
    __syncthreads();
#pragma unroll
    for (int i = 0; i < 8; i++) {
        int id2 = t + i * 256;
        int n = id2 >> 5, f = id2 & 31;
        float4 v = *(float4*)&Ct[n * CSTR + f * 4];
        *(float4*)&D[(size_t)(n0 + n) * OUTC + o0 + f * 4] = v;
    }
}

// ---------------------------------------------------------------------------
// Attention (round-8 version, unchanged)
// ---------------------------------------------------------------------------
#define TPIX   14
#define NPIX   (TPIX*TPIX)
#define SSTR   197
#define ATTN_SMEM (2 * 8 * SSTR * 16 + CG * KK * 4)   // 51328 B

__global__ __launch_bounds__(128) void attn_kernel(const float* __restrict__ relh,
                                                   const float* __restrict__ relw,
                                                   float* __restrict__ out) {
    extern __shared__ float4 smbuf[];
    float4* ks   = smbuf;
    float4* vs   = smbuf + 8 * SSTR;
    float*  bias = (float*)(smbuf + 16 * SSTR);

    const int b    = blockIdx.z;
    const int g    = blockIdx.y;
    const int tile = blockIdx.x;
    const int ty0  = (tile / 7) * 8;
    const int tx0  = (tile % 7) * 8;
    const int t    = threadIdx.x;
    const int p    = t >> 1;
    const int half = t & 1;

    const float* rel = (g < 4) ? (relh + (size_t)g * CG * KK)
                               : (relw + (size_t)(g - 4) * CG * KK);
    for (int i = t; i < CG * KK; i += 128) bias[i] = rel[i];

    for (int idx = t; idx < NPIX * 8; idx += 128) {
        int c4 = idx & 7;
        int pp = idx >> 3;
        int py = pp / TPIX, px = pp - py * TPIX;
        int yy = ty0 + py - PADV, xx = tx0 + px - PADV;
        float4 kv = make_float4(0.f, 0.f, 0.f, 0.f);
        float4 vv = make_float4(0.f, 0.f, 0.f, 0.f);
        if (yy >= 0 && yy < HH && xx >= 0 && xx < WW) {
            size_t gbase = ((size_t)b * NQ + yy * WW + xx) * OUTC + g * CG;
            kv = *((const float4*)&g_k[gbase] + c4);
            vv = *((const float4*)&g_v[gbase] + c4);
        }
        ks[c4 * SSTR + pp] = kv;
        vs[c4 * SSTR + pp] = vv;
    }
    __syncthreads();

    const int lty = p >> 3, ltx = p & 7;
    const int h = ty0 + lty, w = tx0 + ltx;
    const int pbase = lty * TPIX + ltx;
    const int c4b = half * 4;

    float qf[16];
    {
        const float4* qp = (const float4*)&g_q[((size_t)b * NQ + h * WW + w) * OUTC + g * CG];
#pragma unroll
        for (int c4 = 0; c4 < 4; c4++) {
            float4 v = qp[c4b + c4];
            qf[c4 * 4 + 0] = v.x; qf[c4 * 4 + 1] = v.y;
            qf[c4 * 4 + 2] = v.z; qf[c4 * 4 + 3] = v.w;
        }
    }

    float db[KK];
#pragma unroll
    for (int i = 0; i < KK; i++) {
        float s = 0.f;
#pragma unroll
        for (int c = 0; c < 16; c++) s += qf[c] * bias[(half * 16 + c) * KK + i];
        db[i] = s;
    }
#pragma unroll
    for (int i = 0; i < KK; i++) db[i] += __shfl_xor_sync(0xffffffffu, db[i], 1);

    float lg[KK * KK];
#pragma unroll
    for (int n = 0; n < KK * KK; n++) {
        const int i = n / KK, j = n % KK;
        const int pp = pbase + i * TPIX + j;
        float s = 0.f;
#pragma unroll
        for (int c4 = 0; c4 < 4; c4++) {
            float4 kv = ks[(c4b + c4) * SSTR + pp];
            s += qf[c4 * 4 + 0] * kv.x + qf[c4 * 4 + 1] * kv.y
               + qf[c4 * 4 + 2] * kv.z + qf[c4 * 4 + 3] * kv.w;
        }
        lg[n] = s;
    }
#pragma unroll
    for (int n = 0; n < KK * KK; n++)
        lg[n] += __shfl_xor_sync(0xffffffffu, lg[n], 1);
#pragma unroll
    for (int n = 0; n < KK * KK; n++)
        lg[n] += (g < 4) ? db[n / KK] : db[n % KK];

    float mx = lg[0];
#pragma unroll
    for (int n = 1; n < KK * KK; n++) mx = fmaxf(mx, lg[n]);
    float sum = 0.f;
#pragma unroll
    for (int n = 0; n < KK * KK; n++) { lg[n] = __expf(lg[n] - mx); sum += lg[n]; }
    float inv = 1.f / sum;
#pragma unroll
    for (int n = 0; n < KK * KK; n++) lg[n] *= inv;

#pragma unroll
    for (int c4 = 0; c4 < 4; c4++) {
        float4 acc = make_float4(0.f, 0.f, 0.f, 0.f);
#pragma unroll
        for (int n = 0; n < KK * KK; n++) {
            const int pp = pbase + (n / KK) * TPIX + (n % KK);
            float4 vv = vs[(c4b + c4) * SSTR + pp];
            acc.x += lg[n] * vv.x;
            acc.y += lg[n] * vv.y;
            acc.z += lg[n] * vv.z;
            acc.w += lg[n] * vv.w;
        }
        size_t base = ((size_t)(b * OUTC + g * CG + (c4b + c4) * 4)) * NQ + h * WW + w;
        out[base]          = acc.x;
        out[base + NQ]     = acc.y;
        out[base + 2 * NQ] = acc.z;
        out[base + 3 * NQ] = acc.w;
    }
}

// ---------------------------------------------------------------------------
// Launch
// ---------------------------------------------------------------------------
extern "C" void kernel_launch(void* const* d_in, const int* in_sizes, int n_in,
                              void* d_out, int out_size) {
    const float* fm = (const float*)d_in[0];
    const float* wq = (const float*)d_in[1];
    const float* wk = (const float*)d_in[2];
    const float* wv = (const float*)d_in[3];
    const float* rh = (const float*)d_in[4];
    const float* rw = (const float*)d_in[5];
    float* out = (float*)d_out;

    cudaFuncSetAttribute(attn_kernel, cudaFuncAttributeMaxDynamicSharedMemorySize, ATTN_SMEM);
    cudaFuncSetAttribute(gemm_all,    cudaFuncAttributeMaxDynamicSharedMemorySize, G_SMEMB);

    prep_w<<<(3 * 256 * 128 + 255) / 256, 256>>>(wq, wk, wv);
    gemm_all<<<TOT_TILES, 256, G_SMEMB>>>(fm);
    attn_kernel<<<dim3(49, GRP, BB), 128, ATTN_SMEM>>>(rh, rw, out);
}

// round 11
// speedup vs baseline: 1.7491x; 1.1303x over previous
#include <cuda_runtime.h>
#include <cstdint>

// ---------------------------------------------------------------------------
// Problem constants
// ---------------------------------------------------------------------------
#define BB    2
#define CIN   256
#define HH    56
#define WW    56
#define OUTC  256
#define KK    7
#define PADV  3
#define GRP   8
#define CG    32
#define NQ    (HH*WW)     // 3136 = 49*64

#define KT    32          // fp32 channels per k-tile
#define STR2  20          // A SMEM u32 stride per row (16 words + 4 pad)
#define BSTRB 144         // B SMEM byte stride per k-row (128B data + 16 pad)
#define CSTR  132         // epilogue transpose stride

#define TPB   196
#define TOT_TILES (3*TPB) // 588

#define W_ITEMS (3*256*128)        // weight u32 words
#define X_ITEMS (1024*784)         // fm float4 units (2b * 512ch * 784)
#define PREP_T  (W_ITEMS + X_ITEMS)

// ---------------------------------------------------------------------------
// helpers (portable sm_80+ PTX)
// ---------------------------------------------------------------------------
__device__ __forceinline__ void mma16(float* c, const uint32_t* a, const uint32_t* b) {
    asm volatile("mma.sync.aligned.m16n8k16.row.col.f32.bf16.bf16.f32 "
        "{%0,%1,%2,%3}, {%4,%5,%6,%7}, {%8,%9}, {%0,%1,%2,%3};"
        : "+f"(c[0]), "+f"(c[1]), "+f"(c[2]), "+f"(c[3])
        : "r"(a[0]), "r"(a[1]), "r"(a[2]), "r"(a[3]), "r"(b[0]), "r"(b[1]));
}
__device__ __forceinline__ uint32_t pk_bf2(float hi_f, float lo_f) {
    uint32_t r;
    asm("cvt.rn.bf16x2.f32 %0, %1, %2;" : "=r"(r) : "f"(hi_f), "f"(lo_f));
    return r;
}
__device__ __forceinline__ float bf_lo_f(uint32_t w) { return __uint_as_float(w << 16); }
__device__ __forceinline__ float bf_hi_f(uint32_t w) { return __uint_as_float(w & 0xFFFF0000u); }

__device__ __forceinline__ uint32_t smem_u32(const void* p) {
    return (uint32_t)__cvta_generic_to_shared(p);
}
__device__ __forceinline__ void cpa16(uint32_t dst, const void* src) {
    asm volatile("cp.async.ca.shared.global [%0], [%1], 16;" :: "r"(dst), "l"(src));
}
#define CPA_COMMIT() asm volatile("cp.async.commit_group;" ::: "memory")
#define CPA_WAIT0()  asm volatile("cp.async.wait_group 0;"  ::: "memory")
#define CPA_WAIT1()  asm volatile("cp.async.wait_group 1;"  ::: "memory")

// ldmatrix: A fragment (m16k16) from [row][k-word] layout, byte-base abase
__device__ __forceinline__ void ldsmA(uint32_t* f, uint32_t abase, int mb, int kw0, int l) {
    uint32_t addr = abase + (uint32_t)(((mb + (l & 15)) * STR2 + kw0 + ((l >> 2) & 4)) * 4);
    asm volatile("ldmatrix.sync.aligned.m8n8.x4.shared.b16 {%0,%1,%2,%3}, [%4];"
        : "=r"(f[0]), "=r"(f[1]), "=r"(f[2]), "=r"(f[3]) : "r"(addr));
}
// ldmatrix trans: B fragment (n8k16) from k-major [k][n bf16] layout
__device__ __forceinline__ void ldsmBt(uint32_t* f, uint32_t bbase, int nb, int k0, int l) {
    uint32_t addr = bbase + (uint32_t)((k0 + (l & 15)) * BSTRB + nb * 2);
    asm volatile("ldmatrix.sync.aligned.m8n8.x2.trans.shared.b16 {%0,%1}, [%2];"
        : "=r"(f[0]), "=r"(f[1]) : "r"(addr));
}

// ---------------------------------------------------------------------------
// Scratch (device globals)
// ---------------------------------------------------------------------------
__device__ float g_q[BB * NQ * OUTC];
__device__ float g_k[BB * NQ * OUTC];
__device__ float g_v[BB * NQ * OUTC];
__device__ uint32_t g_wh[3 * 256 * 128];     // weight bf16x2 hi: [type][o][kw]
__device__ uint32_t g_wl[3 * 256 * 128];     // weight bf16x2 lo
__device__ uint32_t g_xh[1024 * 1568];       // fm bf16 hi: [row=b*512+c][n/2] (n-pairs)
__device__ uint32_t g_xl[1024 * 1568];       // fm bf16 lo

// ---------------------------------------------------------------------------
// 0) Prep: weights AND fm -> bf16 hi/lo (element-wise, coalesced)
// ---------------------------------------------------------------------------
__global__ void prep_all(const float* __restrict__ fm, const float* __restrict__ wq,
                         const float* __restrict__ wk, const float* __restrict__ wv) {
    int idx = blockIdx.x * blockDim.x + threadIdx.x;
    if (idx < W_ITEMS) {
        int type = idx / (256 * 128);
        int rem  = idx % (256 * 128);
        const float* W = (type == 0) ? wq : (type == 1) ? wk : wv;
        float2 v = *(const float2*)&W[(size_t)rem * 2];
        uint32_t wh = pk_bf2(v.y, v.x);
        float l0 = v.x - bf_lo_f(wh), l1 = v.y - bf_hi_f(wh);
        g_wh[idx] = wh;
        g_wl[idx] = pk_bf2(l1, l0);
    } else {
        int j = idx - W_ITEMS;
        if (j >= X_ITEMS) return;
        int row = j / 784, n4 = j % 784;
        float4 v = *(const float4*)&fm[(size_t)row * NQ + n4 * 4];
        uint32_t h0 = pk_bf2(v.y, v.x);
        uint32_t h1 = pk_bf2(v.w, v.z);
        float l0 = v.x - bf_lo_f(h0), l1 = v.y - bf_hi_f(h0);
        float l2 = v.z - bf_lo_f(h1), l3 = v.w - bf_hi_f(h1);
        size_t o = (size_t)row * 1568 + n4 * 2;
        *(uint2*)&g_xh[o] = make_uint2(h0, h1);
        *(uint2*)&g_xl[o] = make_uint2(pk_bf2(l1, l0), pk_bf2(l3, l2));
    }
}

// ---------------------------------------------------------------------------
// Fused GEMM: 3xBF16 m16n8k16, all-cp.async (A and B pre-converted),
// ldmatrix(+trans for B), 3-stage pipeline. Tile 128(o) x 64(n); 8 warps 4x2.
// ---------------------------------------------------------------------------
#define A_W     (128 * STR2)               // 2560 u32 per A buffer
#define AH_OFF  0
#define AL_OFF  (A_W * 4)                  // 10240 B
#define BH_OFF  (2 * A_W * 4)              // 20480 B
#define BL_OFF  (BH_OFF + 32 * BSTRB)      // 25088 B
#define STAGE_B (BL_OFF + 32 * BSTRB)      // 29696 B
#define NSTG    3
#define G_SMEMB (NSTG * STAGE_B)           // 89088 B

__global__ __launch_bounds__(256, 2) void gemm_all(void) {
    extern __shared__ uint32_t smu[];
    const uint32_t sbase = smem_u32(smu);

    const int t  = threadIdx.x;
    const int id = blockIdx.x;

    const int type  = id / TPB;           // 0=Q, 1=K, 2=V
    const int local = id % TPB;
    const int ni_t = local % 49;
    const int rest = local / 49;
    const int o0 = (rest & 1) * 128;
    const int b  = rest >> 1;
    const int n0 = ni_t * 64;

    float* D = ((type == 0) ? g_q : (type == 1) ? g_k : g_v) + (size_t)b * NQ * OUTC;
    const uint32_t* WHrow = g_wh + ((size_t)type * 256 + o0) * 128;
    const uint32_t* WLrow = g_wl + ((size_t)type * 256 + o0) * 128;
    const int srcrow0 = b * 512 + (type == 0 ? 256 : 0);   // fm row base

    const int wid = t >> 5, l = t & 31;
    const int m0w = (wid & 3) * 32;
    const int n0w = (wid >> 2) * 32;
    const int am = t >> 2, af = t & 3;             // A cp.async role
    const int brow = t >> 3, bchunk = t & 7;       // B cp.async role

    float c[2][4][4];
#pragma unroll
    for (int mi = 0; mi < 2; mi++)
#pragma unroll
        for (int ni = 0; ni < 4; ni++)
#pragma unroll
            for (int e = 0; e < 4; e++) c[mi][ni][e] = 0.f;

    // issue all cp.async for k-tile `ktile` into stage byte-base stb (+1 commit)
#define STAGE_LOAD(stb, ktile)                                                     \
    {                                                                              \
        int kw = (ktile) * 16;                                                     \
        _Pragma("unroll")                                                          \
        for (int i = 0; i < 2; i++) {                                              \
            int m = am + i * 64;                                                   \
            uint32_t doff = (uint32_t)((m * STR2 + af * 4) * 4);                   \
            cpa16((stb) + AH_OFF + doff, WHrow + (size_t)m * 128 + kw + af * 4);   \
            cpa16((stb) + AL_OFF + doff, WLrow + (size_t)m * 128 + kw + af * 4);   \
        }                                                                          \
        {                                                                          \
            size_t srcoff = ((size_t)(srcrow0 + (ktile) * KT + brow) * NQ          \
                             + n0 + bchunk * 8) * 2;                               \
            uint32_t doff = (uint32_t)(brow * BSTRB + bchunk * 16);                \
            cpa16((stb) + BH_OFF + doff, (const char*)g_xh + srcoff);              \
            cpa16((stb) + BL_OFF + doff, (const char*)g_xl + srcoff);              \
        }                                                                          \
        CPA_COMMIT();                                                              \
    }

    // ---- prologue: stages 0 and 1 in flight ----
    STAGE_LOAD(sbase, 0);
    STAGE_LOAD(sbase + STAGE_B, 1);
    CPA_WAIT1();                   // stage 0 complete
    __syncthreads();

#pragma unroll 1
    for (int kt = 0; kt < CIN / KT; kt++) {
        const int s = kt % NSTG;
        const uint32_t stb = sbase + (uint32_t)(s * STAGE_B);
        const uint32_t aH = stb + AH_OFF;
        const uint32_t aL = stb + AL_OFF;
        const uint32_t bH = stb + BH_OFF;
        const uint32_t bL = stb + BL_OFF;

        if (kt + 2 < CIN / KT) {
            STAGE_LOAD(sbase + (uint32_t)(((kt + 2) % NSTG) * STAGE_B), kt + 2);
        }

        // MMAs on current stage: 2 k16-steps
#pragma unroll
        for (int ks = 0; ks < 2; ks++) {
            const int kw0 = ks * 8;          // A word offset
            const int k0  = ks * 16;         // B row offset
            uint32_t ah0[4], ah1[4], al0[4], al1[4];
            ldsmA(ah0, aH, m0w,      kw0, l);
            ldsmA(ah1, aH, m0w + 16, kw0, l);
            ldsmA(al0, aL, m0w,      kw0, l);
            ldsmA(al1, aL, m0w + 16, kw0, l);
#pragma unroll
            for (int ni = 0; ni < 4; ni++) {
                uint32_t bh[2], bl[2];
                ldsmBt(bh, bH, n0w + ni * 8, k0, l);
                ldsmBt(bl, bL, n0w + ni * 8, k0, l);
                mma16(c[0][ni], ah0, bh);
                mma16(c[0][ni], ah0, bl);
                mma16(c[0][ni], al0, bh);
                mma16(c[1][ni], ah1, bh);
                mma16(c[1][ni], ah1, bl);
                mma16(c[1][ni], al1, bh);
            }
        }

        if (kt + 2 < CIN / KT) { CPA_WAIT1(); } else { CPA_WAIT0(); }
        __syncthreads();
    }

    // Epilogue: transpose through SMEM -> coalesced channel-last stores
    const int r = l >> 2, q = l & 3;
    float* Ct = (float*)smu;                 // [64 n][CSTR]
#pragma unroll
    for (int mi = 0; mi < 2; mi++)
#pragma unroll
        for (int ni = 0; ni < 4; ni++) {
            int m = m0w + mi * 16 + r;
            int n = n0w + ni * 8 + q * 2;
            Ct[(n)     * CSTR + m]     = c[mi][ni][0];
            Ct[(n + 1) * CSTR + m]     = c[mi][ni][1];
            Ct[(n)     * CSTR + m + 8] = c[mi][ni][2];
            Ct[(n + 1) * CSTR + m + 8] = c[mi][ni][3];
        }
    __syncthreads();
#pragma unroll
    for (int i = 0; i < 8; i++) {
        int id2 = t + i * 256;
        int n = id2 >> 5, f = id2 & 31;
        float4 v = *(float4*)&Ct[n * CSTR + f * 4];
        *(float4*)&D[(size_t)(n0 + n) * OUTC + o0 + f * 4] = v;
    }
}

// ---------------------------------------------------------------------------
// Attention (round-8 version, unchanged)
// ---------------------------------------------------------------------------
#define TPIX   14
#define NPIX   (TPIX*TPIX)
#define SSTR   197
#define ATTN_SMEM (2 * 8 * SSTR * 16 + CG * KK * 4)   // 51328 B

__global__ __launch_bounds__(128) void attn_kernel(const float* __restrict__ relh,
                                                   const float* __restrict__ relw,
                                                   float* __restrict__ out) {
    extern __shared__ float4 smbuf[];
    float4* ks   = smbuf;
    float4* vs   = smbuf + 8 * SSTR;
    float*  bias = (float*)(smbuf + 16 * SSTR);

    const int b    = blockIdx.z;
    const int g    = blockIdx.y;
    const int tile = blockIdx.x;
    const int ty0  = (tile / 7) * 8;
    const int tx0  = (tile % 7) * 8;
    const int t    = threadIdx.x;
    const int p    = t >> 1;
    const int half = t & 1;

    const float* rel = (g < 4) ? (relh + (size_t)g * CG * KK)
                               : (relw + (size_t)(g - 4) * CG * KK);
    for (int i = t; i < CG * KK; i += 128) bias[i] = rel[i];

    for (int idx = t; idx < NPIX * 8; idx += 128) {
        int c4 = idx & 7;
        int pp = idx >> 3;
        int py = pp / TPIX, px = pp - py * TPIX;
        int yy = ty0 + py - PADV, xx = tx0 + px - PADV;
        float4 kv = make_float4(0.f, 0.f, 0.f, 0.f);
        float4 vv = make_float4(0.f, 0.f, 0.f, 0.f);
        if (yy >= 0 && yy < HH && xx >= 0 && xx < WW) {
            size_t gbase = ((size_t)b * NQ + yy * WW + xx) * OUTC + g * CG;
            kv = *((const float4*)&g_k[gbase] + c4);
            vv = *((const float4*)&g_v[gbase] + c4);
        }
        ks[c4 * SSTR + pp] = kv;
        vs[c4 * SSTR + pp] = vv;
    }
    __syncthreads();

    const int lty = p >> 3, ltx = p & 7;
    const int h = ty0 + lty, w = tx0 + ltx;
    const int pbase = lty * TPIX + ltx;
    const int c4b = half * 4;

    float qf[16];
    {
        const float4* qp = (const float4*)&g_q[((size_t)b * NQ + h * WW + w) * OUTC + g * CG];
#pragma unroll
        for (int c4 = 0; c4 < 4; c4++) {
            float4 v = qp[c4b + c4];
            qf[c4 * 4 + 0] = v.x; qf[c4 * 4 + 1] = v.y;
            qf[c4 * 4 + 2] = v.z; qf[c4 * 4 + 3] = v.w;
        }
    }

    float db[KK];
#pragma unroll
    for (int i = 0; i < KK; i++) {
        float s = 0.f;
#pragma unroll
        for (int c = 0; c < 16; c++) s += qf[c] * bias[(half * 16 + c) * KK + i];
        db[i] = s;
    }
#pragma unroll
    for (int i = 0; i < KK; i++) db[i] += __shfl_xor_sync(0xffffffffu, db[i], 1);

    float lg[KK * KK];
#pragma unroll
    for (int n = 0; n < KK * KK; n++) {
        const int i = n / KK, j = n % KK;
        const int pp = pbase + i * TPIX + j;
        float s = 0.f;
#pragma unroll
        for (int c4 = 0; c4 < 4; c4++) {
            float4 kv = ks[(c4b + c4) * SSTR + pp];
            s += qf[c4 * 4 + 0] * kv.x + qf[c4 * 4 + 1] * kv.y
               + qf[c4 * 4 + 2] * kv.z + qf[c4 * 4 + 3] * kv.w;
        }
        lg[n] = s;
    }
#pragma unroll
    for (int n = 0; n < KK * KK; n++)
        lg[n] += __shfl_xor_sync(0xffffffffu, lg[n], 1);
#pragma unroll
    for (int n = 0; n < KK * KK; n++)
        lg[n] += (g < 4) ? db[n / KK] : db[n % KK];

    float mx = lg[0];
#pragma unroll
    for (int n = 1; n < KK * KK; n++) mx = fmaxf(mx, lg[n]);
    float sum = 0.f;
#pragma unroll
    for (int n = 0; n < KK * KK; n++) { lg[n] = __expf(lg[n] - mx); sum += lg[n]; }
    float inv = 1.f / sum;
#pragma unroll
    for (int n = 0; n < KK * KK; n++) lg[n] *= inv;

#pragma unroll
    for (int c4 = 0; c4 < 4; c4++) {
        float4 acc = make_float4(0.f, 0.f, 0.f, 0.f);
#pragma unroll
        for (int n = 0; n < KK * KK; n++) {
            const int pp = pbase + (n / KK) * TPIX + (n % KK);
            float4 vv = vs[(c4b + c4) * SSTR + pp];
            acc.x += lg[n] * vv.x;
            acc.y += lg[n] * vv.y;
            acc.z += lg[n] * vv.z;
            acc.w += lg[n] * vv.w;
        }
        size_t base = ((size_t)(b * OUTC + g * CG + (c4b + c4) * 4)) * NQ + h * WW + w;
        out[base]          = acc.x;
        out[base + NQ]     = acc.y;
        out[base + 2 * NQ] = acc.z;
        out[base + 3 * NQ] = acc.w;
    }
}

// ---------------------------------------------------------------------------
// Launch
// ---------------------------------------------------------------------------
extern "C" void kernel_launch(void* const* d_in, const int* in_sizes, int n_in,
                              void* d_out, int out_size) {
    const float* fm = (const float*)d_in[0];
    const float* wq = (const float*)d_in[1];
    const float* wk = (const float*)d_in[2];
    const float* wv = (const float*)d_in[3];
    const float* rh = (const float*)d_in[4];
    const float* rw = (const float*)d_in[5];
    float* out = (float*)d_out;

    cudaFuncSetAttribute(attn_kernel, cudaFuncAttributeMaxDynamicSharedMemorySize, ATTN_SMEM);
    cudaFuncSetAttribute(gemm_all,    cudaFuncAttributeMaxDynamicSharedMemorySize, G_SMEMB);

    prep_all<<<(PREP_T + 255) / 256, 256>>>(fm, wq, wk, wv);
    gemm_all<<<TOT_TILES, 256, G_SMEMB>>>();
    attn_kernel<<<dim3(49, GRP, BB), 128, ATTN_SMEM>>>(rh, rw, out);
}